// round 3
// baseline (speedup 1.0000x reference)
#include <cuda_runtime.h>
#include <cstdint>
#include <cstddef>

// Problem shapes (fixed): B=64, T=512, D=512, N=1024, 4N=4096
#define BB 64
#define TT 512
#define DD 512
#define NN 1024
#define GG 4096

// ---------------------------------------------------------------------------
// Device-global scratch (sanctioned mechanism; no runtime allocation)
// ---------------------------------------------------------------------------
__device__ float    g_xp[(size_t)TT * BB * GG];   // [T][B][4N] input projections (536 MB)
__device__ float    g_hbuf[2][BB * NN];           // parity double-buffered h (tf32-rounded)
__device__ unsigned g_flags[128 * 8];             // per-CTA step flags, padded to 32B

// ---------------------------------------------------------------------------
// Helpers
// ---------------------------------------------------------------------------
static __device__ __forceinline__ unsigned f2b(float f) { return __float_as_uint(f); }

static __device__ __forceinline__ unsigned tf32u(float f) {
    unsigned u;
    asm("cvt.rna.tf32.f32 %0, %1;" : "=r"(u) : "f"(f));
    return u;
}
static __device__ __forceinline__ float tf32f(float f) { return __uint_as_float(tf32u(f)); }

static __device__ __forceinline__ float sigf(float x) { return 1.0f / (1.0f + __expf(-x)); }
static __device__ __forceinline__ float tanh_fast(float x) { return 2.0f * sigf(2.0f * x) - 1.0f; }

static __device__ __forceinline__ unsigned smaddr(const void* p) {
    return (unsigned)__cvta_generic_to_shared(p);
}
#define CP16(d, s)  asm volatile("cp.async.cg.shared.global [%0], [%1], 16;" :: "r"(d), "l"(s))
#define CPCOMMIT()  asm volatile("cp.async.commit_group;")

static __device__ __forceinline__ void mma8(float* d, const unsigned* a, unsigned b0, unsigned b1) {
    asm volatile(
        "mma.sync.aligned.m16n8k8.row.col.f32.tf32.tf32.f32 "
        "{%0,%1,%2,%3},{%4,%5,%6,%7},{%8,%9},{%0,%1,%2,%3};"
        : "+f"(d[0]), "+f"(d[1]), "+f"(d[2]), "+f"(d[3])
        : "r"(a[0]), "r"(a[1]), "r"(a[2]), "r"(a[3]), "r"(b0), "r"(b1));
}

static __device__ __forceinline__ unsigned ld_acq(const unsigned* p) {
    unsigned v;
    asm volatile("ld.global.acquire.gpu.u32 %0, [%1];" : "=r"(v) : "l"(p));
    return v;
}
static __device__ __forceinline__ void st_rel(unsigned* p, unsigned v) {
    asm volatile("st.global.release.gpu.u32 [%0], %1;" :: "l"(p), "r"(v));
}

// ---------------------------------------------------------------------------
// Init: h ring parity-0 <- tf32(h0); zero barrier flags. Runs every replay.
// ---------------------------------------------------------------------------
__global__ void init_kernel(const float* __restrict__ h0) {
    int i = blockIdx.x * 256 + threadIdx.x;       // 65536 threads == BB*NN
    g_hbuf[0][i] = tf32f(h0[i]);
    if (i < 128 * 8) g_flags[i] = 0u;
}

// ---------------------------------------------------------------------------
// Phase 1: xp = x @ [Wfx|Wix|Wox|Wcx] + bias, written as [T][B][4N]
// grid (256 m-blocks, 32 n-blocks), 256 threads, tf32 mma, BM=BN=128 BK=32
// ---------------------------------------------------------------------------
#define P1_AST 36      // A smem stride (floats): bank = (4*row + col) % 32 -> conflict-free
#define P1_BST 136     // B smem stride (floats): bank = (8*k + n) % 32   -> conflict-free
#define P1_SMEMF (2 * 128 * P1_AST + 2 * 32 * P1_BST)        // floats
#define P1_SMEMB (P1_SMEMF * 4)                              // 71680 bytes

__global__ void __launch_bounds__(256, 2) xproj_kernel(
    const float* __restrict__ x,
    const float* __restrict__ Wfx, const float* __restrict__ bf,
    const float* __restrict__ Wix, const float* __restrict__ bi,
    const float* __restrict__ Wox, const float* __restrict__ bo,
    const float* __restrict__ Wcx, const float* __restrict__ bc)
{
    extern __shared__ float sm[];
    float* AsP = sm;                        // [2][128][P1_AST]
    float* BsP = sm + 2 * 128 * P1_AST;     // [2][32][P1_BST]

    const int tid  = threadIdx.x;
    const int warp = tid >> 5, lane = tid & 31;
    const int g    = lane >> 2, tig = lane & 3;
    const int wm   = warp >> 1, wn = warp & 1;   // 4x2 warp grid
    const int M0   = blockIdx.x * 128;
    const int gate = blockIdx.y >> 3;
    const int nc0  = (blockIdx.y & 7) * 128;     // column within this gate's [D,N] matrix
    const float* W    = (gate == 0) ? Wfx : (gate == 1) ? Wix : (gate == 2) ? Wox : Wcx;
    const float* bias = (gate == 0) ? bf  : (gate == 1) ? bi  : (gate == 2) ? bo  : bc;

    float acc[2][8][4];
    #pragma unroll
    for (int a = 0; a < 2; a++)
        #pragma unroll
        for (int b = 0; b < 8; b++)
            #pragma unroll
            for (int q = 0; q < 4; q++) acc[a][b][q] = 0.0f;

    auto stage = [&](int chunk, int buf) {
        const int k0 = chunk * 32;
        float* Ad = AsP + buf * 128 * P1_AST;
        #pragma unroll
        for (int i = 0; i < 4; i++) {
            int s = tid + 256 * i;               // 0..1023 ; A tile 128 rows x 8 16B-segs
            int row = s >> 3, off = (s & 7) * 4;
            CP16(smaddr(Ad + row * P1_AST + off), x + (size_t)(M0 + row) * DD + k0 + off);
        }
        float* Bd = BsP + buf * 32 * P1_BST;
        #pragma unroll
        for (int i = 0; i < 4; i++) {
            int s = tid + 256 * i;               // B tile 32 rows x 32 16B-segs
            int row = s >> 5, off = (s & 31) * 4;
            CP16(smaddr(Bd + row * P1_BST + off), W + (size_t)(k0 + row) * NN + nc0 + off);
        }
        CPCOMMIT();
    };

    stage(0, 0);
    for (int c = 0; c < 16; c++) {
        if (c + 1 < 16) {
            stage(c + 1, (c + 1) & 1);
            asm volatile("cp.async.wait_group 1;");
        } else {
            asm volatile("cp.async.wait_group 0;");
        }
        __syncthreads();
        const float* A  = AsP + (c & 1) * 128 * P1_AST;
        const float* Bm = BsP + (c & 1) * 32 * P1_BST;
        #pragma unroll
        for (int kk = 0; kk < 4; kk++) {
            unsigned a[2][4];
            #pragma unroll
            for (int mf = 0; mf < 2; mf++) {
                int rb = wm * 32 + mf * 16;
                a[mf][0] = tf32u(A[(rb + g)     * P1_AST + kk * 8 + tig]);
                a[mf][1] = tf32u(A[(rb + g + 8) * P1_AST + kk * 8 + tig]);
                a[mf][2] = tf32u(A[(rb + g)     * P1_AST + kk * 8 + tig + 4]);
                a[mf][3] = tf32u(A[(rb + g + 8) * P1_AST + kk * 8 + tig + 4]);
            }
            #pragma unroll
            for (int nf = 0; nf < 8; nf++) {
                int nb = wn * 64 + nf * 8;
                unsigned b0 = tf32u(Bm[(kk * 8 + tig)     * P1_BST + nb + g]);
                unsigned b1 = tf32u(Bm[(kk * 8 + tig + 4) * P1_BST + nb + g]);
                mma8(acc[0][nf], a[0], b0, b1);
                mma8(acc[1][nf], a[1], b0, b1);
            }
        }
        __syncthreads();   // protect buf (c&1) before it is restaged next iteration
    }

    // Epilogue: add bias, scatter to g_xp[t][b][4N]  (rows m = b*T + t)
    #pragma unroll
    for (int mf = 0; mf < 2; mf++) {
        #pragma unroll
        for (int rr = 0; rr < 2; rr++) {
            int m = M0 + wm * 32 + mf * 16 + g + rr * 8;
            int b = m >> 9, t = m & 511;
            size_t base = ((size_t)t * BB + b) * GG + (size_t)blockIdx.y * 128;
            #pragma unroll
            for (int nf = 0; nf < 8; nf++) {
                int col = wn * 64 + nf * 8 + 2 * tig;
                float v0 = acc[mf][nf][rr * 2 + 0] + bias[nc0 + col];
                float v1 = acc[mf][nf][rr * 2 + 1] + bias[nc0 + col + 1];
                *(float2*)&g_xp[base + col] = make_float2(v0, v1);
            }
        }
    }
}

// ---------------------------------------------------------------------------
// Phase 2: persistent LSTM recurrence. 128 CTAs x 128 threads (all resident).
// CTA j owns n-indices [8j, 8j+8): 32 gate-columns of Wh resident in SMEM,
// pre-permuted to mma-fragment order (2x LDS.128 per k-step, conflict-free).
// ---------------------------------------------------------------------------
#define P2_WHF    32768                 // floats: 128 ksteps x 32 lanes x 8 (two float4 arrays)
#define P2_AST    68                    // A smem stride: bank = (4*row + col) % 32, conflict-free
#define P2_ASZ    (2 * 16 * P2_AST)     // per-warp double-buffered A chunk (floats)
#define P2_SMEMB  ((P2_WHF + 4 * P2_ASZ) * 4)   // 165888 bytes

__global__ void __launch_bounds__(128, 1) lstm_kernel(
    const float* __restrict__ c0,
    const float* __restrict__ Wfh, const float* __restrict__ Wih,
    const float* __restrict__ Woh, const float* __restrict__ Wch,
    const float* __restrict__ wcf, const float* __restrict__ wci,
    const float* __restrict__ wco,
    float* __restrict__ out)
{
    extern __shared__ float sm[];
    float* whff = sm;                                    // raw fill view
    const float4* whfA = (const float4*)sm;              // [ks*32+lane] -> (b0,b1 gate f, b0,b1 gate i)
    const float4* whfB = whfA + 128 * 32;                // gates o, c
    float* Asw = sm + P2_WHF + (threadIdx.x >> 5) * P2_ASZ;

    const int tid  = threadIdx.x;
    const int warp = tid >> 5, lane = tid & 31;
    const int g    = lane >> 2, tig = lane & 3;
    const int cta  = blockIdx.x;
    const int n0   = cta * 8;

    // --- Prologue: build tf32 Wh fragments in SMEM (resident for all 512 steps)
    for (int e = tid; e < 32768; e += 128) {
        int j    = e & 3;
        int ln   = (e >> 2) & 31;
        int ks   = (e >> 7) & 127;
        int half = e >> 14;
        int nt   = half * 2 + (j >> 1);    // gate: 0=f 1=i 2=o 3=c
        int cb   = j & 1;                  // b0 / b1
        int k    = ks * 8 + (ln & 3) + 4 * cb;
        int col  = n0 + (ln >> 2);
        const float* Wsel = (nt == 0) ? Wfh : (nt == 1) ? Wih : (nt == 2) ? Woh : Wch;
        whff[e] = tf32f(Wsel[(size_t)k * NN + col]);
    }

    // --- Per-thread state: 2 b-rows x 2 n-cols of (c, peephole weights)
    const int bA = 16 * warp + g;
    const int bB = bA + 8;
    const int nA = n0 + 2 * tig;

    float2 cA = *(const float2*)&c0[bA * NN + nA];
    float2 cB = *(const float2*)&c0[bB * NN + nA];
    float creg[2][2] = {{cA.x, cA.y}, {cB.x, cB.y}};
    float2 pf2 = *(const float2*)&wcf[nA];
    float2 pi2 = *(const float2*)&wci[nA];
    float2 po2 = *(const float2*)&wco[nA];
    const float pfv[2] = {pf2.x, pf2.y};
    const float piv[2] = {pi2.x, pi2.y};
    const float pov[2] = {po2.x, po2.y};

    __syncthreads();   // whf ready

    const int wrow0 = 16 * warp;

    for (int t = 0; t < TT; t++) {
        const float* hsrc = g_hbuf[t & 1];
        float* hdst = g_hbuf[(t + 1) & 1];

        // Prefetch this step's xp slice (independent of h -> hidden under GEMM)
        const float* xpt = g_xp + (size_t)t * BB * GG;
        float2 xv[4][2];
        #pragma unroll
        for (int nt = 0; nt < 4; nt++) {
            xv[nt][0] = *(const float2*)&xpt[(size_t)bA * GG + nt * NN + nA];
            xv[nt][1] = *(const float2*)&xpt[(size_t)bB * GG + nt * NN + nA];
        }

        float acc[4][4];
        #pragma unroll
        for (int a = 0; a < 4; a++) { acc[a][0] = acc[a][1] = acc[a][2] = acc[a][3] = 0.0f; }

        // Per-warp double-buffered h streaming: 16 chunks of K=64
        auto stageh = [&](int chunk, int buf) {
            const float* src = hsrc + wrow0 * NN + chunk * 64;
            float* dst = Asw + buf * (16 * P2_AST);
            #pragma unroll
            for (int i = 0; i < 8; i++) {
                int s = lane + 32 * i;              // 16 rows x 16 16B-segs
                int row = s >> 4, off = (s & 15) * 4;
                CP16(smaddr(dst + row * P2_AST + off), src + row * NN + off);
            }
            CPCOMMIT();
        };

        stageh(0, 0);
        for (int c = 0; c < 16; c++) {
            if (c + 1 < 16) { stageh(c + 1, (c + 1) & 1); asm volatile("cp.async.wait_group 1;"); }
            else            { asm volatile("cp.async.wait_group 0;"); }
            __syncwarp();
            const float* A = Asw + (c & 1) * (16 * P2_AST);
            #pragma unroll
            for (int kk = 0; kk < 8; kk++) {
                int ks = c * 8 + kk;
                unsigned a[4];
                a[0] = f2b(A[g       * P2_AST + kk * 8 + tig]);
                a[1] = f2b(A[(g + 8) * P2_AST + kk * 8 + tig]);
                a[2] = f2b(A[g       * P2_AST + kk * 8 + tig + 4]);
                a[3] = f2b(A[(g + 8) * P2_AST + kk * 8 + tig + 4]);
                float4 u0 = whfA[ks * 32 + lane];
                float4 u1 = whfB[ks * 32 + lane];
                mma8(acc[0], a, f2b(u0.x), f2b(u0.y));   // forget gate
                mma8(acc[1], a, f2b(u0.z), f2b(u0.w));   // input gate
                mma8(acc[2], a, f2b(u1.x), f2b(u1.y));   // output gate
                mma8(acc[3], a, f2b(u1.z), f2b(u1.w));   // cell candidate
            }
            __syncwarp();   // all lanes done reading buf (c&1) before it is restaged
        }

        // Fused peephole cell update + stores
        #pragma unroll
        for (int rr = 0; rr < 2; rr++) {
            const int b = rr ? bB : bA;
            float hv[2], hr[2];
            #pragma unroll
            for (int q = 0; q < 2; q++) {
                const int j = rr * 2 + q;
                float xf = ((const float*)&xv[0][rr])[q];
                float xi = ((const float*)&xv[1][rr])[q];
                float xo = ((const float*)&xv[2][rr])[q];
                float xc = ((const float*)&xv[3][rr])[q];
                float cp = creg[rr][q];
                float fg = sigf(xf + acc[0][j] + pfv[q] * cp);
                float ig = sigf(xi + acc[1][j] + piv[q] * cp);
                float ct = tanh_fast(xc + acc[3][j]);
                float cn = fg * cp + ig * ct;
                float og = sigf(xo + acc[2][j] + pov[q] * cn);
                float hn = og * tanh_fast(cn);
                creg[rr][q] = cn;
                hv[q] = hn;
                hr[q] = tf32f(hn);
            }
            *(float2*)&out[((size_t)b * TT + t) * NN + nA] = make_float2(hv[0], hv[1]);
            *(float2*)&hdst[b * NN + nA]                   = make_float2(hr[0], hr[1]);
        }

        // Distributed-flag inter-CTA barrier (one per step)
        __syncthreads();
        if (tid == 0) st_rel(&g_flags[cta * 8], (unsigned)(t + 1));
        {
            const unsigned tgt = (unsigned)(t + 1);
            while (ld_acq(&g_flags[tid * 8]) < tgt) { }
        }
        __syncthreads();
    }
}

// ---------------------------------------------------------------------------
// Launch. Input order is detected from in_sizes: the harness serializes inputs
// either in setup_inputs() dict order or in reference() signature order. The
// two differ at index 5: dict order has Wix (D*N = 524288 elems) there,
// signature order has Wfh (N*N = 1048576 elems).
// ---------------------------------------------------------------------------
extern "C" void kernel_launch(void* const* d_in, const int* in_sizes, int n_in,
                              void* d_out, int out_size) {
    const float* x   = (const float*)d_in[0];
    const float* c0  = (const float*)d_in[1];
    const float* h0  = (const float*)d_in[2];

    const float *Wfx, *bf, *Wix, *bi, *Wox, *bo, *Wcx, *bc;
    const float *Wfh, *Wih, *Woh, *Wch, *wcf, *wci, *wco;

    if (in_sizes[5] == NN * NN) {
        // signature order: Wfx, bf, Wfh, Wix, bi, Wih, Wox, bo, Woh, Wcx, bc, Wch, wcf, wci, wco
        Wfx = (const float*)d_in[3];  bf  = (const float*)d_in[4];  Wfh = (const float*)d_in[5];
        Wix = (const float*)d_in[6];  bi  = (const float*)d_in[7];  Wih = (const float*)d_in[8];
        Wox = (const float*)d_in[9];  bo  = (const float*)d_in[10]; Woh = (const float*)d_in[11];
        Wcx = (const float*)d_in[12]; bc  = (const float*)d_in[13]; Wch = (const float*)d_in[14];
        wcf = (const float*)d_in[15]; wci = (const float*)d_in[16]; wco = (const float*)d_in[17];
    } else {
        // dict order: Wfx, bf, Wix, bi, Wox, bo, Wcx, bc, Wfh, Wih, Woh, Wch, wcf, wci, wco
        Wfx = (const float*)d_in[3];  bf  = (const float*)d_in[4];
        Wix = (const float*)d_in[5];  bi  = (const float*)d_in[6];
        Wox = (const float*)d_in[7];  bo  = (const float*)d_in[8];
        Wcx = (const float*)d_in[9];  bc  = (const float*)d_in[10];
        Wfh = (const float*)d_in[11]; Wih = (const float*)d_in[12];
        Woh = (const float*)d_in[13]; Wch = (const float*)d_in[14];
        wcf = (const float*)d_in[15]; wci = (const float*)d_in[16]; wco = (const float*)d_in[17];
    }
    float* out = (float*)d_out;

    cudaFuncSetAttribute(xproj_kernel, cudaFuncAttributeMaxDynamicSharedMemorySize, P1_SMEMB);
    cudaFuncSetAttribute(lstm_kernel,  cudaFuncAttributeMaxDynamicSharedMemorySize, P2_SMEMB);

    init_kernel<<<256, 256>>>(h0);

    dim3 g1(256, 32);
    xproj_kernel<<<g1, 256, P1_SMEMB>>>(x, Wfx, bf, Wix, bi, Wox, bo, Wcx, bc);

    lstm_kernel<<<128, 128, P2_SMEMB>>>(c0, Wfh, Wih, Woh, Wch, wcf, wci, wco, out);
}

// round 4
// speedup vs baseline: 1.0423x; 1.0423x over previous
#include <cuda_runtime.h>
#include <cstdint>
#include <cstddef>

// Problem shapes (fixed): B=64, T=512, D=512, N=1024, 4N=4096
#define BB 64
#define TT 512
#define DD 512
#define NN 1024
#define GG 4096

// ---------------------------------------------------------------------------
// Device-global scratch
// ---------------------------------------------------------------------------
__device__ float    g_xp[(size_t)TT * BB * GG];   // [T][B][4N] input projections
__device__ float    g_hbuf[2][BB * NN];           // parity double-buffered h (tf32-rounded)
__device__ unsigned g_flags[128 * 8];             // per-CTA step flags, padded to 32B

// ---------------------------------------------------------------------------
// Helpers
// ---------------------------------------------------------------------------
static __device__ __forceinline__ unsigned f2b(float f) { return __float_as_uint(f); }

static __device__ __forceinline__ unsigned tf32u(float f) {
    unsigned u;
    asm("cvt.rna.tf32.f32 %0, %1;" : "=r"(u) : "f"(f));
    return u;
}
static __device__ __forceinline__ float tf32f(float f) { return __uint_as_float(tf32u(f)); }

static __device__ __forceinline__ float sigf(float x) { return 1.0f / (1.0f + __expf(-x)); }
static __device__ __forceinline__ float tanh_fast(float x) { return 2.0f * sigf(2.0f * x) - 1.0f; }

static __device__ __forceinline__ unsigned smaddr(const void* p) {
    return (unsigned)__cvta_generic_to_shared(p);
}
#define CP16(d, s)  asm volatile("cp.async.cg.shared.global [%0], [%1], 16;" :: "r"(d), "l"(s))
#define CPCOMMIT()  asm volatile("cp.async.commit_group;")

template <int NPend>
static __device__ __forceinline__ void cpwait() {
    asm volatile("cp.async.wait_group %0;" :: "n"(NPend));
}

static __device__ __forceinline__ void mma8(float* d, const unsigned* a, unsigned b0, unsigned b1) {
    asm volatile(
        "mma.sync.aligned.m16n8k8.row.col.f32.tf32.tf32.f32 "
        "{%0,%1,%2,%3},{%4,%5,%6,%7},{%8,%9},{%0,%1,%2,%3};"
        : "+f"(d[0]), "+f"(d[1]), "+f"(d[2]), "+f"(d[3])
        : "r"(a[0]), "r"(a[1]), "r"(a[2]), "r"(a[3]), "r"(b0), "r"(b1));
}

static __device__ __forceinline__ unsigned ld_acq(const unsigned* p) {
    unsigned v;
    asm volatile("ld.global.acquire.gpu.u32 %0, [%1];" : "=r"(v) : "l"(p));
    return v;
}
static __device__ __forceinline__ void st_rel(unsigned* p, unsigned v) {
    asm volatile("st.global.release.gpu.u32 [%0], %1;" :: "l"(p), "r"(v));
}

// ---------------------------------------------------------------------------
// Init: h ring parity-0 <- tf32(h0); zero barrier flags. Runs every replay.
// ---------------------------------------------------------------------------
__global__ void init_kernel(const float* __restrict__ h0) {
    int i = blockIdx.x * 256 + threadIdx.x;       // 65536 threads == BB*NN
    g_hbuf[0][i] = tf32f(h0[i]);
    if (i < 128 * 8) g_flags[i] = 0u;
}

// ---------------------------------------------------------------------------
// Phase 1: xp = x @ [Wfx|Wix|Wox|Wcx] + bias, written as [T][B][4N]
// grid (256 m-blocks, 32 n-blocks), 256 threads, tf32 mma, BM=BN=128 BK=32
// ---------------------------------------------------------------------------
#define P1_AST 36
#define P1_BST 136
#define P1_SMEMF (2 * 128 * P1_AST + 2 * 32 * P1_BST)
#define P1_SMEMB (P1_SMEMF * 4)

__global__ void __launch_bounds__(256, 2) xproj_kernel(
    const float* __restrict__ x,
    const float* __restrict__ Wfx, const float* __restrict__ bf,
    const float* __restrict__ Wix, const float* __restrict__ bi,
    const float* __restrict__ Wox, const float* __restrict__ bo,
    const float* __restrict__ Wcx, const float* __restrict__ bc)
{
    extern __shared__ float sm[];
    float* AsP = sm;                        // [2][128][P1_AST]
    float* BsP = sm + 2 * 128 * P1_AST;     // [2][32][P1_BST]

    const int tid  = threadIdx.x;
    const int warp = tid >> 5, lane = tid & 31;
    const int g    = lane >> 2, tig = lane & 3;
    const int wm   = warp >> 1, wn = warp & 1;
    const int M0   = blockIdx.x * 128;
    const int gate = blockIdx.y >> 3;
    const int nc0  = (blockIdx.y & 7) * 128;
    const float* W    = (gate == 0) ? Wfx : (gate == 1) ? Wix : (gate == 2) ? Wox : Wcx;
    const float* bias = (gate == 0) ? bf  : (gate == 1) ? bi  : (gate == 2) ? bo  : bc;

    float acc[2][8][4];
    #pragma unroll
    for (int a = 0; a < 2; a++)
        #pragma unroll
        for (int b = 0; b < 8; b++)
            #pragma unroll
            for (int q = 0; q < 4; q++) acc[a][b][q] = 0.0f;

    auto stage = [&](int chunk, int buf) {
        const int k0 = chunk * 32;
        float* Ad = AsP + buf * 128 * P1_AST;
        #pragma unroll
        for (int i = 0; i < 4; i++) {
            int s = tid + 256 * i;
            int row = s >> 3, off = (s & 7) * 4;
            CP16(smaddr(Ad + row * P1_AST + off), x + (size_t)(M0 + row) * DD + k0 + off);
        }
        float* Bd = BsP + buf * 32 * P1_BST;
        #pragma unroll
        for (int i = 0; i < 4; i++) {
            int s = tid + 256 * i;
            int row = s >> 5, off = (s & 31) * 4;
            CP16(smaddr(Bd + row * P1_BST + off), W + (size_t)(k0 + row) * NN + nc0 + off);
        }
        CPCOMMIT();
    };

    stage(0, 0);
    for (int c = 0; c < 16; c++) {
        if (c + 1 < 16) { stage(c + 1, (c + 1) & 1); cpwait<1>(); }
        else            { cpwait<0>(); }
        __syncthreads();
        const float* A  = AsP + (c & 1) * 128 * P1_AST;
        const float* Bm = BsP + (c & 1) * 32 * P1_BST;
        #pragma unroll
        for (int kk = 0; kk < 4; kk++) {
            unsigned a[2][4];
            #pragma unroll
            for (int mf = 0; mf < 2; mf++) {
                int rb = wm * 32 + mf * 16;
                a[mf][0] = tf32u(A[(rb + g)     * P1_AST + kk * 8 + tig]);
                a[mf][1] = tf32u(A[(rb + g + 8) * P1_AST + kk * 8 + tig]);
                a[mf][2] = tf32u(A[(rb + g)     * P1_AST + kk * 8 + tig + 4]);
                a[mf][3] = tf32u(A[(rb + g + 8) * P1_AST + kk * 8 + tig + 4]);
            }
            #pragma unroll
            for (int nf = 0; nf < 8; nf++) {
                int nb = wn * 64 + nf * 8;
                unsigned b0 = tf32u(Bm[(kk * 8 + tig)     * P1_BST + nb + g]);
                unsigned b1 = tf32u(Bm[(kk * 8 + tig + 4) * P1_BST + nb + g]);
                mma8(acc[0][nf], a[0], b0, b1);
                mma8(acc[1][nf], a[1], b0, b1);
            }
        }
        __syncthreads();
    }

    #pragma unroll
    for (int mf = 0; mf < 2; mf++) {
        #pragma unroll
        for (int rr = 0; rr < 2; rr++) {
            int m = M0 + wm * 32 + mf * 16 + g + rr * 8;
            int b = m >> 9, t = m & 511;
            size_t base = ((size_t)t * BB + b) * GG + (size_t)blockIdx.y * 128;
            #pragma unroll
            for (int nf = 0; nf < 8; nf++) {
                int col = wn * 64 + nf * 8 + 2 * tig;
                float v0 = acc[mf][nf][rr * 2 + 0] + bias[nc0 + col];
                float v1 = acc[mf][nf][rr * 2 + 1] + bias[nc0 + col + 1];
                *(float2*)&g_xp[base + col] = make_float2(v0, v1);
            }
        }
    }
}

// ---------------------------------------------------------------------------
// Phase 2: persistent LSTM recurrence. 128 CTAs x 128 threads.
// K-SPLIT: warp w handles k in [256w, 256w+256) for ALL 64 batch rows.
// Each Wh fragment read once per CTA per step (no 4x redundancy).
// 4-deep cp.async pipeline over 16 chunks of 32 rows x 32 k-cols.
// Cross-warp reduction in smem (reusing A staging region), then identical
// per-thread cell update as before (thread (warp, lane) owns rows 16*warp+g).
// ---------------------------------------------------------------------------
#define P2_WHF    32768                  // Wh fragments: 128 ksteps x 32 lanes x 8 floats
#define P2_CHF    (32 * 36)              // one chunk: 32 rows x stride 36 = 1152 floats
#define P2_ASZ    (4 * P2_CHF)           // 4-stage ring per warp = 4608 floats
#define P2_SMEMF  (P2_WHF + 4 * P2_ASZ)  // 51200 floats
#define P2_SMEMB  (P2_SMEMF * 4)         // 204800 bytes

__global__ void __launch_bounds__(128, 1) lstm_kernel(
    const float* __restrict__ c0,
    const float* __restrict__ Wfh, const float* __restrict__ Wih,
    const float* __restrict__ Woh, const float* __restrict__ Wch,
    const float* __restrict__ wcf, const float* __restrict__ wci,
    const float* __restrict__ wco,
    float* __restrict__ out)
{
    extern __shared__ float sm[];
    float* whff = sm;                                    // raw fill view
    const float4* whfA = (const float4*)sm;              // gates f,i : [ks*32+lane]
    const float4* whfB = whfA + 128 * 32;                // gates o,c
    float* Aswbase = sm + P2_WHF;                        // 4 warp regions of P2_ASZ

    const int tid  = threadIdx.x;
    const int warp = tid >> 5, lane = tid & 31;
    const int g    = lane >> 2, tig = lane & 3;
    const int cta  = blockIdx.x;
    const int n0   = cta * 8;

    float* Asw = Aswbase + warp * P2_ASZ;

    // --- Prologue: build tf32 Wh fragments in SMEM (resident for all steps)
    for (int e = tid; e < 32768; e += 128) {
        int j    = e & 3;
        int ln   = (e >> 2) & 31;
        int ks   = (e >> 7) & 127;
        int half = e >> 14;
        int nt   = half * 2 + (j >> 1);    // gate: 0=f 1=i 2=o 3=c
        int cb   = j & 1;                  // b0 / b1
        int k    = ks * 8 + (ln & 3) + 4 * cb;
        int col  = n0 + (ln >> 2);
        const float* Wsel = (nt == 0) ? Wfh : (nt == 1) ? Wih : (nt == 2) ? Woh : Wch;
        whff[e] = tf32f(Wsel[(size_t)k * NN + col]);
    }

    // --- Per-thread state: rows bA/bB, cols nA..nA+1
    const int bA = 16 * warp + g;
    const int bB = bA + 8;
    const int nA = n0 + 2 * tig;

    float2 cA = *(const float2*)&c0[bA * NN + nA];
    float2 cB = *(const float2*)&c0[bB * NN + nA];
    float creg[2][2] = {{cA.x, cA.y}, {cB.x, cB.y}};
    float2 pf2 = *(const float2*)&wcf[nA];
    float2 pi2 = *(const float2*)&wci[nA];
    float2 po2 = *(const float2*)&wco[nA];
    const float pfv[2] = {pf2.x, pf2.y};
    const float piv[2] = {pi2.x, pi2.y};
    const float pov[2] = {po2.x, po2.y};

    __syncthreads();   // whf ready

    const int kbase = warp * 256;      // this warp's k-column base

    for (int t = 0; t < TT; t++) {
        const float* hsrc = g_hbuf[t & 1];
        float* hdst = g_hbuf[(t + 1) & 1];

        // Accumulators: acc[mf][gate][q], mf covers all 64 b-rows
        float acc[4][4][4] __attribute__((aligned(16)));
        #pragma unroll
        for (int a = 0; a < 4; a++)
            #pragma unroll
            for (int b = 0; b < 4; b++)
                #pragma unroll
                for (int q = 0; q < 4; q++) acc[a][b][q] = 0.0f;

        // Stage chunk ci: rows (ci&1)*32..+32, k-cols kbase + (ci>>1)*32..+32
        auto stageh = [&](int ci) {
            const int rh = ci & 1, kc = ci >> 1;
            const float* src = hsrc + (size_t)(rh * 32) * NN + kbase + kc * 32;
            float* dst = Asw + (ci & 3) * P2_CHF;
            #pragma unroll
            for (int i = 0; i < 8; i++) {
                int s = lane + 32 * i;              // 32 rows x 8 16B-segs
                int row = s >> 3, off = (s & 7) * 4;
                CP16(smaddr(dst + row * 36 + off), src + (size_t)row * NN + off);
            }
            CPCOMMIT();
        };
        auto waitfor = [&](int ci) {
            if (ci < 13)      cpwait<3>();
            else if (ci == 13) cpwait<2>();
            else if (ci == 14) cpwait<1>();
            else               cpwait<0>();
        };

        stageh(0); stageh(1); stageh(2);

        float4 u0[4], u1[4];                   // Wh fragments for current kc (4 ksteps)

        #pragma unroll 2
        for (int kc = 0; kc < 8; kc++) {
            // ---- rh = 0 chunk (ci = 2*kc) ----
            {
                const int ci = 2 * kc;
                if (ci + 3 < 16) stageh(ci + 3);
                waitfor(ci);
                __syncwarp();
                // hoist this kc's Wh fragments (used by both rh chunks)
                #pragma unroll
                for (int kk = 0; kk < 4; kk++) {
                    int ks = warp * 32 + kc * 4 + kk;
                    u0[kk] = whfA[ks * 32 + lane];
                    u1[kk] = whfB[ks * 32 + lane];
                }
                const float* A = Asw + (ci & 3) * P2_CHF;
                #pragma unroll
                for (int kk = 0; kk < 4; kk++) {
                    #pragma unroll
                    for (int mfp = 0; mfp < 2; mfp++) {
                        unsigned a[4];
                        a[0] = f2b(A[(16 * mfp + g)     * 36 + kk * 8 + tig]);
                        a[1] = f2b(A[(16 * mfp + g + 8) * 36 + kk * 8 + tig]);
                        a[2] = f2b(A[(16 * mfp + g)     * 36 + kk * 8 + tig + 4]);
                        a[3] = f2b(A[(16 * mfp + g + 8) * 36 + kk * 8 + tig + 4]);
                        mma8(acc[mfp][0], a, f2b(u0[kk].x), f2b(u0[kk].y));
                        mma8(acc[mfp][1], a, f2b(u0[kk].z), f2b(u0[kk].w));
                        mma8(acc[mfp][2], a, f2b(u1[kk].x), f2b(u1[kk].y));
                        mma8(acc[mfp][3], a, f2b(u1[kk].z), f2b(u1[kk].w));
                    }
                }
                __syncwarp();
            }
            // ---- rh = 1 chunk (ci = 2*kc+1) ----
            {
                const int ci = 2 * kc + 1;
                if (ci + 3 < 16) stageh(ci + 3);
                waitfor(ci);
                __syncwarp();
                const float* A = Asw + (ci & 3) * P2_CHF;
                #pragma unroll
                for (int kk = 0; kk < 4; kk++) {
                    #pragma unroll
                    for (int mfp = 0; mfp < 2; mfp++) {
                        unsigned a[4];
                        a[0] = f2b(A[(16 * mfp + g)     * 36 + kk * 8 + tig]);
                        a[1] = f2b(A[(16 * mfp + g + 8) * 36 + kk * 8 + tig]);
                        a[2] = f2b(A[(16 * mfp + g)     * 36 + kk * 8 + tig + 4]);
                        a[3] = f2b(A[(16 * mfp + g + 8) * 36 + kk * 8 + tig + 4]);
                        mma8(acc[2 + mfp][0], a, f2b(u0[kk].x), f2b(u0[kk].y));
                        mma8(acc[2 + mfp][1], a, f2b(u0[kk].z), f2b(u0[kk].w));
                        mma8(acc[2 + mfp][2], a, f2b(u1[kk].x), f2b(u1[kk].y));
                        mma8(acc[2 + mfp][3], a, f2b(u1[kk].z), f2b(u1[kk].w));
                    }
                }
                __syncwarp();
            }
        }

        // Prefetch xp (latency hidden under reduction)
        const float* xpt = g_xp + (size_t)t * BB * GG;
        float2 xv[4][2];
        #pragma unroll
        for (int nt = 0; nt < 4; nt++) {
            xv[nt][0] = *(const float2*)&xpt[(size_t)bA * GG + nt * NN + nA];
            xv[nt][1] = *(const float2*)&xpt[(size_t)bB * GG + nt * NN + nA];
        }

        // --- Cross-warp reduction via smem (reuse own A staging region)
        #pragma unroll
        for (int mf = 0; mf < 4; mf++)
            #pragma unroll
            for (int gt = 0; gt < 4; gt++)
                *(float4*)&Asw[((mf * 4 + gt) * 32 + lane) * 4] = *(const float4*)acc[mf][gt];
        __syncthreads();

        float fin[4][4];
        #pragma unroll
        for (int gt = 0; gt < 4; gt++) {
            float4 s = make_float4(0.f, 0.f, 0.f, 0.f);
            #pragma unroll
            for (int w = 0; w < 4; w++) {
                float4 v = *(const float4*)&Aswbase[w * P2_ASZ + ((warp * 4 + gt) * 32 + lane) * 4];
                s.x += v.x; s.y += v.y; s.z += v.z; s.w += v.w;
            }
            fin[gt][0] = s.x; fin[gt][1] = s.y; fin[gt][2] = s.z; fin[gt][3] = s.w;
        }

        // --- Fused peephole cell update + stores
        #pragma unroll
        for (int rr = 0; rr < 2; rr++) {
            const int b = rr ? bB : bA;
            float hv[2], hr[2];
            #pragma unroll
            for (int q = 0; q < 2; q++) {
                const int j = rr * 2 + q;
                float xf = ((const float*)&xv[0][rr])[q];
                float xi = ((const float*)&xv[1][rr])[q];
                float xo = ((const float*)&xv[2][rr])[q];
                float xc = ((const float*)&xv[3][rr])[q];
                float cp = creg[rr][q];
                float fg = sigf(xf + fin[0][j] + pfv[q] * cp);
                float ig = sigf(xi + fin[1][j] + piv[q] * cp);
                float ct = tanh_fast(xc + fin[3][j]);
                float cn = fg * cp + ig * ct;
                float og = sigf(xo + fin[2][j] + pov[q] * cn);
                float hn = og * tanh_fast(cn);
                creg[rr][q] = cn;
                hv[q] = hn;
                hr[q] = tf32f(hn);
            }
            *(float2*)&out[((size_t)b * TT + t) * NN + nA] = make_float2(hv[0], hv[1]);
            *(float2*)&hdst[b * NN + nA]                   = make_float2(hr[0], hr[1]);
        }

        // --- Distributed-flag inter-CTA barrier (one per step)
        __syncthreads();
        if (tid == 0) st_rel(&g_flags[cta * 8], (unsigned)(t + 1));
        {
            const unsigned tgt = (unsigned)(t + 1);
            while (ld_acq(&g_flags[tid * 8]) < tgt) { }
        }
        __syncthreads();
    }
}

// ---------------------------------------------------------------------------
// Launch. Input order detected from in_sizes (dict vs signature order).
// ---------------------------------------------------------------------------
extern "C" void kernel_launch(void* const* d_in, const int* in_sizes, int n_in,
                              void* d_out, int out_size) {
    const float* x   = (const float*)d_in[0];
    const float* c0  = (const float*)d_in[1];
    const float* h0  = (const float*)d_in[2];

    const float *Wfx, *bf, *Wix, *bi, *Wox, *bo, *Wcx, *bc;
    const float *Wfh, *Wih, *Woh, *Wch, *wcf, *wci, *wco;

    if (in_sizes[5] == NN * NN) {
        Wfx = (const float*)d_in[3];  bf  = (const float*)d_in[4];  Wfh = (const float*)d_in[5];
        Wix = (const float*)d_in[6];  bi  = (const float*)d_in[7];  Wih = (const float*)d_in[8];
        Wox = (const float*)d_in[9];  bo  = (const float*)d_in[10]; Woh = (const float*)d_in[11];
        Wcx = (const float*)d_in[12]; bc  = (const float*)d_in[13]; Wch = (const float*)d_in[14];
        wcf = (const float*)d_in[15]; wci = (const float*)d_in[16]; wco = (const float*)d_in[17];
    } else {
        Wfx = (const float*)d_in[3];  bf  = (const float*)d_in[4];
        Wix = (const float*)d_in[5];  bi  = (const float*)d_in[6];
        Wox = (const float*)d_in[7];  bo  = (const float*)d_in[8];
        Wcx = (const float*)d_in[9];  bc  = (const float*)d_in[10];
        Wfh = (const float*)d_in[11]; Wih = (const float*)d_in[12];
        Woh = (const float*)d_in[13]; Wch = (const float*)d_in[14];
        wcf = (const float*)d_in[15]; wci = (const float*)d_in[16]; wco = (const float*)d_in[17];
    }
    float* out = (float*)d_out;

    cudaFuncSetAttribute(xproj_kernel, cudaFuncAttributeMaxDynamicSharedMemorySize, P1_SMEMB);
    cudaFuncSetAttribute(lstm_kernel,  cudaFuncAttributeMaxDynamicSharedMemorySize, P2_SMEMB);

    init_kernel<<<256, 256>>>(h0);

    dim3 g1(256, 32);
    xproj_kernel<<<g1, 256, P1_SMEMB>>>(x, Wfx, bf, Wix, bi, Wox, bo, Wcx, bc);

    lstm_kernel<<<128, 128, P2_SMEMB>>>(c0, Wfh, Wih, Woh, Wch, wcf, wci, wco, out);
}

// round 5
// speedup vs baseline: 1.1097x; 1.0647x over previous
#include <cuda_runtime.h>
#include <cstdint>
#include <cstddef>

// Problem shapes (fixed): B=64, T=512, D=512, N=1024, 4N=4096
#define BB 64
#define TT 512
#define DD 512
#define NN 1024
#define GG 4096

// ---------------------------------------------------------------------------
// Device-global scratch
// ---------------------------------------------------------------------------
__device__ float    g_xp[(size_t)TT * BB * GG];   // [T][B][4N] input projections
__device__ float    g_hbuf[2][BB * NN];           // parity double-buffered h (tf32-rounded)
__device__ unsigned g_flags[128 * 8];             // per-CTA step flags, padded to 32B

// ---------------------------------------------------------------------------
// Helpers
// ---------------------------------------------------------------------------
static __device__ __forceinline__ unsigned f2b(float f) { return __float_as_uint(f); }

static __device__ __forceinline__ unsigned tf32u(float f) {
    unsigned u;
    asm("cvt.rna.tf32.f32 %0, %1;" : "=r"(u) : "f"(f));
    return u;
}
static __device__ __forceinline__ float tf32f(float f) { return __uint_as_float(tf32u(f)); }

static __device__ __forceinline__ float sigf(float x) { return 1.0f / (1.0f + __expf(-x)); }
static __device__ __forceinline__ float tanh_fast(float x) { return 2.0f * sigf(2.0f * x) - 1.0f; }

static __device__ __forceinline__ unsigned smaddr(const void* p) {
    return (unsigned)__cvta_generic_to_shared(p);
}
#define CP16(d, s)  asm volatile("cp.async.cg.shared.global [%0], [%1], 16;" :: "r"(d), "l"(s))
#define CPCOMMIT()  asm volatile("cp.async.commit_group;")

template <int NPend>
static __device__ __forceinline__ void cpwait() {
    asm volatile("cp.async.wait_group %0;" :: "n"(NPend));
}

static __device__ __forceinline__ void mma8(float* d, const unsigned* a, unsigned b0, unsigned b1) {
    asm volatile(
        "mma.sync.aligned.m16n8k8.row.col.f32.tf32.tf32.f32 "
        "{%0,%1,%2,%3},{%4,%5,%6,%7},{%8,%9},{%0,%1,%2,%3};"
        : "+f"(d[0]), "+f"(d[1]), "+f"(d[2]), "+f"(d[3])
        : "r"(a[0]), "r"(a[1]), "r"(a[2]), "r"(a[3]), "r"(b0), "r"(b1));
}

static __device__ __forceinline__ unsigned ld_acq(const unsigned* p) {
    unsigned v;
    asm volatile("ld.global.acquire.gpu.u32 %0, [%1];" : "=r"(v) : "l"(p));
    return v;
}
static __device__ __forceinline__ void st_rel(unsigned* p, unsigned v) {
    asm volatile("st.global.release.gpu.u32 [%0], %1;" :: "l"(p), "r"(v));
}

// ---------------------------------------------------------------------------
// Init: h ring parity-0 <- tf32(h0); zero barrier flags. Runs every replay.
// ---------------------------------------------------------------------------
__global__ void init_kernel(const float* __restrict__ h0) {
    int i = blockIdx.x * 256 + threadIdx.x;       // 65536 threads == BB*NN
    g_hbuf[0][i] = tf32f(h0[i]);
    if (i < 128 * 8) g_flags[i] = 0u;
}

// ---------------------------------------------------------------------------
// Phase 1: xp = x @ [Wfx|Wix|Wox|Wcx] + bias, written as [T][B][4N]
// ---------------------------------------------------------------------------
#define P1_AST 36
#define P1_BST 136
#define P1_SMEMF (2 * 128 * P1_AST + 2 * 32 * P1_BST)
#define P1_SMEMB (P1_SMEMF * 4)

__global__ void __launch_bounds__(256, 2) xproj_kernel(
    const float* __restrict__ x,
    const float* __restrict__ Wfx, const float* __restrict__ bf,
    const float* __restrict__ Wix, const float* __restrict__ bi,
    const float* __restrict__ Wox, const float* __restrict__ bo,
    const float* __restrict__ Wcx, const float* __restrict__ bc)
{
    extern __shared__ float sm[];
    float* AsP = sm;                        // [2][128][P1_AST]
    float* BsP = sm + 2 * 128 * P1_AST;     // [2][32][P1_BST]

    const int tid  = threadIdx.x;
    const int warp = tid >> 5, lane = tid & 31;
    const int g    = lane >> 2, tig = lane & 3;
    const int wm   = warp >> 1, wn = warp & 1;
    const int M0   = blockIdx.x * 128;
    const int gate = blockIdx.y >> 3;
    const int nc0  = (blockIdx.y & 7) * 128;
    const float* W    = (gate == 0) ? Wfx : (gate == 1) ? Wix : (gate == 2) ? Wox : Wcx;
    const float* bias = (gate == 0) ? bf  : (gate == 1) ? bi  : (gate == 2) ? bo  : bc;

    float acc[2][8][4];
    #pragma unroll
    for (int a = 0; a < 2; a++)
        #pragma unroll
        for (int b = 0; b < 8; b++)
            #pragma unroll
            for (int q = 0; q < 4; q++) acc[a][b][q] = 0.0f;

    auto stage = [&](int chunk, int buf) {
        const int k0 = chunk * 32;
        float* Ad = AsP + buf * 128 * P1_AST;
        #pragma unroll
        for (int i = 0; i < 4; i++) {
            int s = tid + 256 * i;
            int row = s >> 3, off = (s & 7) * 4;
            CP16(smaddr(Ad + row * P1_AST + off), x + (size_t)(M0 + row) * DD + k0 + off);
        }
        float* Bd = BsP + buf * 32 * P1_BST;
        #pragma unroll
        for (int i = 0; i < 4; i++) {
            int s = tid + 256 * i;
            int row = s >> 5, off = (s & 31) * 4;
            CP16(smaddr(Bd + row * P1_BST + off), W + (size_t)(k0 + row) * NN + nc0 + off);
        }
        CPCOMMIT();
    };

    stage(0, 0);
    for (int c = 0; c < 16; c++) {
        if (c + 1 < 16) { stage(c + 1, (c + 1) & 1); cpwait<1>(); }
        else            { cpwait<0>(); }
        __syncthreads();
        const float* A  = AsP + (c & 1) * 128 * P1_AST;
        const float* Bm = BsP + (c & 1) * 32 * P1_BST;
        #pragma unroll
        for (int kk = 0; kk < 4; kk++) {
            unsigned a[2][4];
            #pragma unroll
            for (int mf = 0; mf < 2; mf++) {
                int rb = wm * 32 + mf * 16;
                a[mf][0] = tf32u(A[(rb + g)     * P1_AST + kk * 8 + tig]);
                a[mf][1] = tf32u(A[(rb + g + 8) * P1_AST + kk * 8 + tig]);
                a[mf][2] = tf32u(A[(rb + g)     * P1_AST + kk * 8 + tig + 4]);
                a[mf][3] = tf32u(A[(rb + g + 8) * P1_AST + kk * 8 + tig + 4]);
            }
            #pragma unroll
            for (int nf = 0; nf < 8; nf++) {
                int nb = wn * 64 + nf * 8;
                unsigned b0 = tf32u(Bm[(kk * 8 + tig)     * P1_BST + nb + g]);
                unsigned b1 = tf32u(Bm[(kk * 8 + tig + 4) * P1_BST + nb + g]);
                mma8(acc[0][nf], a[0], b0, b1);
                mma8(acc[1][nf], a[1], b0, b1);
            }
        }
        __syncthreads();
    }

    #pragma unroll
    for (int mf = 0; mf < 2; mf++) {
        #pragma unroll
        for (int rr = 0; rr < 2; rr++) {
            int m = M0 + wm * 32 + mf * 16 + g + rr * 8;
            int b = m >> 9, t = m & 511;
            size_t base = ((size_t)t * BB + b) * GG + (size_t)blockIdx.y * 128;
            #pragma unroll
            for (int nf = 0; nf < 8; nf++) {
                int col = wn * 64 + nf * 8 + 2 * tig;
                float v0 = acc[mf][nf][rr * 2 + 0] + bias[nc0 + col];
                float v1 = acc[mf][nf][rr * 2 + 1] + bias[nc0 + col + 1];
                *(float2*)&g_xp[base + col] = make_float2(v0, v1);
            }
        }
    }
}

// ---------------------------------------------------------------------------
// Phase 2: persistent LSTM recurrence. 128 CTAs x 256 threads (8 warps,
// 2 warps/SMSP for latency hiding). Warp w owns k in [128w, 128w+128) for
// ALL 64 batch rows: chunks of 16 rows x 32 kcols, 4-deep cp.async ring.
// Wh B-fragments hoisted once per kc, reused across 4 row-chunks.
// Cross-warp (8-way) reduction in smem, then per-thread cell update
// (thread owns 1 row x 2 cols).
// ---------------------------------------------------------------------------
#define P2_WHF    32768                  // Wh fragments: 128 ksteps x 32 lanes x 8 floats
#define P2_CHF    (16 * 36)              // one chunk: 16 rows x stride 36 = 576 floats
#define P2_RING   (4 * P2_CHF)           // 4-stage ring per warp = 2304 floats
#define P2_SMEMF  (P2_WHF + 8 * P2_RING) // 51200 floats
#define P2_SMEMB  (P2_SMEMF * 4)         // 204800 bytes

__global__ void __launch_bounds__(256, 1) lstm_kernel(
    const float* __restrict__ c0,
    const float* __restrict__ Wfh, const float* __restrict__ Wih,
    const float* __restrict__ Woh, const float* __restrict__ Wch,
    const float* __restrict__ wcf, const float* __restrict__ wci,
    const float* __restrict__ wco,
    float* __restrict__ out)
{
    extern __shared__ float sm[];
    float* whff = sm;                                    // raw fill view
    const float4* whfA = (const float4*)sm;              // gates f,i : [ks*32+lane]
    const float4* whfB = whfA + 128 * 32;                // gates o,c
    float* Aswbase = sm + P2_WHF;                        // 8 warp regions of P2_RING

    const int tid  = threadIdx.x;
    const int warp = tid >> 5, lane = tid & 31;
    const int g    = lane >> 2, tig = lane & 3;
    const int cta  = blockIdx.x;
    const int n0   = cta * 8;

    float* Asw = Aswbase + warp * P2_RING;

    // --- Prologue: build tf32 Wh fragments in SMEM (resident for all steps)
    for (int e = tid; e < 32768; e += 256) {
        int j    = e & 3;
        int ln   = (e >> 2) & 31;
        int ks   = (e >> 7) & 127;
        int half = e >> 14;
        int nt   = half * 2 + (j >> 1);    // gate: 0=f 1=i 2=o 3=c
        int cb   = j & 1;                  // b0 / b1
        int k    = ks * 8 + (ln & 3) + 4 * cb;
        int col  = n0 + (ln >> 2);
        const float* Wsel = (nt == 0) ? Wfh : (nt == 1) ? Wih : (nt == 2) ? Woh : Wch;
        whff[e] = tf32f(Wsel[(size_t)k * NN + col]);
    }

    // --- Per-thread update-cell ownership: 1 row x 2 cols
    const int rh_own = warp >> 1;          // 0..3  (row-chunk)
    const int hb     = warp & 1;           // 0..1  (q-half: +0 / +8 rows)
    const int bown   = rh_own * 16 + g + 8 * hb;
    const int nA     = n0 + 2 * tig;

    float2 cv2 = *(const float2*)&c0[bown * NN + nA];
    float creg[2] = {cv2.x, cv2.y};
    float2 pf2 = *(const float2*)&wcf[nA];
    float2 pi2 = *(const float2*)&wci[nA];
    float2 po2 = *(const float2*)&wco[nA];
    const float pfv[2] = {pf2.x, pf2.y};
    const float piv[2] = {pi2.x, pi2.y};
    const float pov[2] = {po2.x, po2.y};

    __syncthreads();   // whf ready

    const int kbase = warp * 128;      // this warp's k-column base

    for (int t = 0; t < TT; t++) {
        const float* hsrc = g_hbuf[t & 1];
        float* hdst = g_hbuf[(t + 1) & 1];

        // Prefetch xp early: latency hides under the whole GEMM
        const float* xpt = g_xp + (size_t)t * BB * GG;
        float2 xv[4];
        #pragma unroll
        for (int nt = 0; nt < 4; nt++)
            xv[nt] = *(const float2*)&xpt[(size_t)bown * GG + nt * NN + nA];

        // Accumulators: acc[rh][gate][q] (rh = row-chunk 0..3)
        float acc[4][4][4] __attribute__((aligned(16)));
        #pragma unroll
        for (int a = 0; a < 4; a++)
            #pragma unroll
            for (int b = 0; b < 4; b++)
                #pragma unroll
                for (int q = 0; q < 4; q++) acc[a][b][q] = 0.0f;

        // Stage chunk ci = kc*4 + rh : rows rh*16..+16, kcols kbase+kc*32..+32
        auto stageh = [&](int ci) {
            const int kc = ci >> 2, rh = ci & 3;
            const float* src = hsrc + (size_t)(rh * 16) * NN + kbase + kc * 32;
            float* dst = Asw + (ci & 3) * P2_CHF;
            #pragma unroll
            for (int i = 0; i < 4; i++) {
                int s = lane + 32 * i;              // 16 rows x 8 16B-segs
                int row = s >> 3, off = (s & 7) * 4;
                CP16(smaddr(dst + row * 36 + off), src + (size_t)row * NN + off);
            }
            CPCOMMIT();
        };
        auto waitfor = [&](int ci) {
            if (ci < 13)       cpwait<3>();
            else if (ci == 13) cpwait<2>();
            else if (ci == 14) cpwait<1>();
            else               cpwait<0>();
        };

        stageh(0); stageh(1); stageh(2);

        float4 u0[4], u1[4];                   // Wh fragments for current kc

        #pragma unroll
        for (int kc = 0; kc < 4; kc++) {
            #pragma unroll
            for (int rh = 0; rh < 4; rh++) {
                const int ci = kc * 4 + rh;
                if (ci + 3 < 16) stageh(ci + 3);
                waitfor(ci);
                __syncwarp();
                if (rh == 0) {
                    #pragma unroll
                    for (int kk = 0; kk < 4; kk++) {
                        int ks = warp * 16 + kc * 4 + kk;
                        u0[kk] = whfA[ks * 32 + lane];
                        u1[kk] = whfB[ks * 32 + lane];
                    }
                }
                const float* A = Asw + (ci & 3) * P2_CHF;
                #pragma unroll
                for (int kk = 0; kk < 4; kk++) {
                    unsigned a[4];
                    a[0] = f2b(A[g       * 36 + kk * 8 + tig]);
                    a[1] = f2b(A[(g + 8) * 36 + kk * 8 + tig]);
                    a[2] = f2b(A[g       * 36 + kk * 8 + tig + 4]);
                    a[3] = f2b(A[(g + 8) * 36 + kk * 8 + tig + 4]);
                    mma8(acc[rh][0], a, f2b(u0[kk].x), f2b(u0[kk].y));
                    mma8(acc[rh][1], a, f2b(u0[kk].z), f2b(u0[kk].w));
                    mma8(acc[rh][2], a, f2b(u1[kk].x), f2b(u1[kk].y));
                    mma8(acc[rh][3], a, f2b(u1[kk].z), f2b(u1[kk].w));
                }
                __syncwarp();
            }
        }

        // --- Cross-warp (8-way) reduction via smem (reuse own ring region)
        // Layout per warp region: [(rh*4+gt)*32 + lane] * 4 floats
        #pragma unroll
        for (int rh = 0; rh < 4; rh++)
            #pragma unroll
            for (int gt = 0; gt < 4; gt++)
                *(float4*)&Asw[((rh * 4 + gt) * 32 + lane) * 4] = *(const float4*)acc[rh][gt];
        __syncthreads();

        float fin[4][2];
        #pragma unroll
        for (int gt = 0; gt < 4; gt++) {
            float2 s = make_float2(0.f, 0.f);
            #pragma unroll
            for (int w = 0; w < 8; w++) {
                float2 v = *(const float2*)&Aswbase[w * P2_RING +
                            ((rh_own * 4 + gt) * 32 + lane) * 4 + hb * 2];
                s.x += v.x; s.y += v.y;
            }
            fin[gt][0] = s.x; fin[gt][1] = s.y;
        }

        // --- Fused peephole cell update + stores (1 row x 2 cols per thread)
        float hv[2], hr[2];
        #pragma unroll
        for (int q = 0; q < 2; q++) {
            float xf = ((const float*)&xv[0])[q];
            float xi = ((const float*)&xv[1])[q];
            float xo = ((const float*)&xv[2])[q];
            float xc = ((const float*)&xv[3])[q];
            float cp = creg[q];
            float fg = sigf(xf + fin[0][q] + pfv[q] * cp);
            float ig = sigf(xi + fin[1][q] + piv[q] * cp);
            float ct = tanh_fast(xc + fin[3][q]);
            float cn = fg * cp + ig * ct;
            float og = sigf(xo + fin[2][q] + pov[q] * cn);
            float hn = og * tanh_fast(cn);
            creg[q] = cn;
            hv[q] = hn;
            hr[q] = tf32f(hn);
        }
        *(float2*)&out[((size_t)bown * TT + t) * NN + nA] = make_float2(hv[0], hv[1]);
        *(float2*)&hdst[bown * NN + nA]                   = make_float2(hr[0], hr[1]);

        // --- Distributed-flag inter-CTA barrier (one per step)
        __syncthreads();
        if (tid == 0) st_rel(&g_flags[cta * 8], (unsigned)(t + 1));
        if (tid < 128) {
            const unsigned tgt = (unsigned)(t + 1);
            while (ld_acq(&g_flags[tid * 8]) < tgt) { }
        }
        __syncthreads();
    }
}

// ---------------------------------------------------------------------------
// Launch. Input order detected from in_sizes (dict vs signature order).
// ---------------------------------------------------------------------------
extern "C" void kernel_launch(void* const* d_in, const int* in_sizes, int n_in,
                              void* d_out, int out_size) {
    const float* x   = (const float*)d_in[0];
    const float* c0  = (const float*)d_in[1];
    const float* h0  = (const float*)d_in[2];

    const float *Wfx, *bf, *Wix, *bi, *Wox, *bo, *Wcx, *bc;
    const float *Wfh, *Wih, *Woh, *Wch, *wcf, *wci, *wco;

    if (in_sizes[5] == NN * NN) {
        Wfx = (const float*)d_in[3];  bf  = (const float*)d_in[4];  Wfh = (const float*)d_in[5];
        Wix = (const float*)d_in[6];  bi  = (const float*)d_in[7];  Wih = (const float*)d_in[8];
        Wox = (const float*)d_in[9];  bo  = (const float*)d_in[10]; Woh = (const float*)d_in[11];
        Wcx = (const float*)d_in[12]; bc  = (const float*)d_in[13]; Wch = (const float*)d_in[14];
        wcf = (const float*)d_in[15]; wci = (const float*)d_in[16]; wco = (const float*)d_in[17];
    } else {
        Wfx = (const float*)d_in[3];  bf  = (const float*)d_in[4];
        Wix = (const float*)d_in[5];  bi  = (const float*)d_in[6];
        Wox = (const float*)d_in[7];  bo  = (const float*)d_in[8];
        Wcx = (const float*)d_in[9];  bc  = (const float*)d_in[10];
        Wfh = (const float*)d_in[11]; Wih = (const float*)d_in[12];
        Woh = (const float*)d_in[13]; Wch = (const float*)d_in[14];
        wcf = (const float*)d_in[15]; wci = (const float*)d_in[16]; wco = (const float*)d_in[17];
    }
    float* out = (float*)d_out;

    cudaFuncSetAttribute(xproj_kernel, cudaFuncAttributeMaxDynamicSharedMemorySize, P1_SMEMB);
    cudaFuncSetAttribute(lstm_kernel,  cudaFuncAttributeMaxDynamicSharedMemorySize, P2_SMEMB);

    init_kernel<<<256, 256>>>(h0);

    dim3 g1(256, 32);
    xproj_kernel<<<g1, 256, P1_SMEMB>>>(x, Wfx, bf, Wix, bi, Wox, bo, Wcx, bc);

    lstm_kernel<<<128, 256, P2_SMEMB>>>(c0, Wfh, Wih, Woh, Wch, wcf, wci, wco, out);
}

// round 6
// speedup vs baseline: 1.2428x; 1.1199x over previous
#include <cuda_runtime.h>
#include <cstdint>
#include <cstddef>

// Problem shapes (fixed): B=64, T=512, D=512, N=1024, 4N=4096
#define BB 64
#define TT 512
#define DD 512
#define NN 1024
#define GG 4096

// ---------------------------------------------------------------------------
// Device-global scratch
// ---------------------------------------------------------------------------
__device__ float    g_xp[(size_t)TT * BB * GG];   // [T][B][4N] input projections
__device__ float    g_hbuf[2][BB * NN];           // parity double-buffered h (tf32-rounded)
__device__ unsigned g_flags[128 * 8];             // per-CTA step flags, padded to 32B

// ---------------------------------------------------------------------------
// Helpers
// ---------------------------------------------------------------------------
static __device__ __forceinline__ unsigned f2b(float f) { return __float_as_uint(f); }

static __device__ __forceinline__ unsigned tf32u(float f) {
    unsigned u;
    asm("cvt.rna.tf32.f32 %0, %1;" : "=r"(u) : "f"(f));
    return u;
}
static __device__ __forceinline__ float tf32f(float f) { return __uint_as_float(tf32u(f)); }

static __device__ __forceinline__ float sigf(float x) { return 1.0f / (1.0f + __expf(-x)); }
static __device__ __forceinline__ float tanh_fast(float x) { return 2.0f * sigf(2.0f * x) - 1.0f; }

static __device__ __forceinline__ unsigned smaddr(const void* p) {
    return (unsigned)__cvta_generic_to_shared(p);
}
#define CP16(d, s)  asm volatile("cp.async.cg.shared.global [%0], [%1], 16;" :: "r"(d), "l"(s))
#define CPCOMMIT()  asm volatile("cp.async.commit_group;")

template <int NPend>
static __device__ __forceinline__ void cpwait() {
    asm volatile("cp.async.wait_group %0;" :: "n"(NPend));
}

static __device__ __forceinline__ void mma8(float* d, const unsigned* a, unsigned b0, unsigned b1) {
    asm volatile(
        "mma.sync.aligned.m16n8k8.row.col.f32.tf32.tf32.f32 "
        "{%0,%1,%2,%3},{%4,%5,%6,%7},{%8,%9},{%0,%1,%2,%3};"
        : "+f"(d[0]), "+f"(d[1]), "+f"(d[2]), "+f"(d[3])
        : "r"(a[0]), "r"(a[1]), "r"(a[2]), "r"(a[3]), "r"(b0), "r"(b1));
}

static __device__ __forceinline__ unsigned ld_acq(const unsigned* p) {
    unsigned v;
    asm volatile("ld.global.acquire.gpu.u32 %0, [%1];" : "=r"(v) : "l"(p));
    return v;
}
static __device__ __forceinline__ void st_rel(unsigned* p, unsigned v) {
    asm volatile("st.global.release.gpu.u32 [%0], %1;" :: "l"(p), "r"(v));
}

// ---------------------------------------------------------------------------
// Init: h ring parity-0 <- tf32(h0); zero barrier flags. Runs every replay.
// ---------------------------------------------------------------------------
__global__ void init_kernel(const float* __restrict__ h0) {
    int i = blockIdx.x * 256 + threadIdx.x;       // 65536 threads == BB*NN
    g_hbuf[0][i] = tf32f(h0[i]);
    if (i < 128 * 8) g_flags[i] = 0u;
}

// ---------------------------------------------------------------------------
// Phase 1: xp = x @ [Wfx|Wix|Wox|Wcx] + bias, written as [T][B][4N]
// ---------------------------------------------------------------------------
#define P1_AST 36
#define P1_BST 136
#define P1_SMEMF (2 * 128 * P1_AST + 2 * 32 * P1_BST)
#define P1_SMEMB (P1_SMEMF * 4)

__global__ void __launch_bounds__(256, 2) xproj_kernel(
    const float* __restrict__ x,
    const float* __restrict__ Wfx, const float* __restrict__ bf,
    const float* __restrict__ Wix, const float* __restrict__ bi,
    const float* __restrict__ Wox, const float* __restrict__ bo,
    const float* __restrict__ Wcx, const float* __restrict__ bc)
{
    extern __shared__ float sm[];
    float* AsP = sm;                        // [2][128][P1_AST]
    float* BsP = sm + 2 * 128 * P1_AST;     // [2][32][P1_BST]

    const int tid  = threadIdx.x;
    const int warp = tid >> 5, lane = tid & 31;
    const int g    = lane >> 2, tig = lane & 3;
    const int wm   = warp >> 1, wn = warp & 1;
    const int M0   = blockIdx.x * 128;
    const int gate = blockIdx.y >> 3;
    const int nc0  = (blockIdx.y & 7) * 128;
    const float* W    = (gate == 0) ? Wfx : (gate == 1) ? Wix : (gate == 2) ? Wox : Wcx;
    const float* bias = (gate == 0) ? bf  : (gate == 1) ? bi  : (gate == 2) ? bo  : bc;

    float acc[2][8][4];
    #pragma unroll
    for (int a = 0; a < 2; a++)
        #pragma unroll
        for (int b = 0; b < 8; b++)
            #pragma unroll
            for (int q = 0; q < 4; q++) acc[a][b][q] = 0.0f;

    auto stage = [&](int chunk, int buf) {
        const int k0 = chunk * 32;
        float* Ad = AsP + buf * 128 * P1_AST;
        #pragma unroll
        for (int i = 0; i < 4; i++) {
            int s = tid + 256 * i;
            int row = s >> 3, off = (s & 7) * 4;
            CP16(smaddr(Ad + row * P1_AST + off), x + (size_t)(M0 + row) * DD + k0 + off);
        }
        float* Bd = BsP + buf * 32 * P1_BST;
        #pragma unroll
        for (int i = 0; i < 4; i++) {
            int s = tid + 256 * i;
            int row = s >> 5, off = (s & 31) * 4;
            CP16(smaddr(Bd + row * P1_BST + off), W + (size_t)(k0 + row) * NN + nc0 + off);
        }
        CPCOMMIT();
    };

    stage(0, 0);
    for (int c = 0; c < 16; c++) {
        if (c + 1 < 16) { stage(c + 1, (c + 1) & 1); cpwait<1>(); }
        else            { cpwait<0>(); }
        __syncthreads();
        const float* A  = AsP + (c & 1) * 128 * P1_AST;
        const float* Bm = BsP + (c & 1) * 32 * P1_BST;
        #pragma unroll
        for (int kk = 0; kk < 4; kk++) {
            unsigned a[2][4];
            #pragma unroll
            for (int mf = 0; mf < 2; mf++) {
                int rb = wm * 32 + mf * 16;
                a[mf][0] = tf32u(A[(rb + g)     * P1_AST + kk * 8 + tig]);
                a[mf][1] = tf32u(A[(rb + g + 8) * P1_AST + kk * 8 + tig]);
                a[mf][2] = tf32u(A[(rb + g)     * P1_AST + kk * 8 + tig + 4]);
                a[mf][3] = tf32u(A[(rb + g + 8) * P1_AST + kk * 8 + tig + 4]);
            }
            #pragma unroll
            for (int nf = 0; nf < 8; nf++) {
                int nb = wn * 64 + nf * 8;
                unsigned b0 = tf32u(Bm[(kk * 8 + tig)     * P1_BST + nb + g]);
                unsigned b1 = tf32u(Bm[(kk * 8 + tig + 4) * P1_BST + nb + g]);
                mma8(acc[0][nf], a[0], b0, b1);
                mma8(acc[1][nf], a[1], b0, b1);
            }
        }
        __syncthreads();
    }

    #pragma unroll
    for (int mf = 0; mf < 2; mf++) {
        #pragma unroll
        for (int rr = 0; rr < 2; rr++) {
            int m = M0 + wm * 32 + mf * 16 + g + rr * 8;
            int b = m >> 9, t = m & 511;
            size_t base = ((size_t)t * BB + b) * GG + (size_t)blockIdx.y * 128;
            #pragma unroll
            for (int nf = 0; nf < 8; nf++) {
                int col = wn * 64 + nf * 8 + 2 * tig;
                float v0 = acc[mf][nf][rr * 2 + 0] + bias[nc0 + col];
                float v1 = acc[mf][nf][rr * 2 + 1] + bias[nc0 + col + 1];
                *(float2*)&g_xp[base + col] = make_float2(v0, v1);
            }
        }
    }
}

// ---------------------------------------------------------------------------
// Phase 2: persistent LSTM recurrence. 128 CTAs x 256 threads (8 warps).
// Warp w owns k in [128w, 128w+128) for ALL 64 batch rows.
//
// FINE-GRAINED DEPENDENCY BARRIER (replaces full per-step barrier):
//   warp w's h-slice (k cols [128w,128w+128)) is produced by CTAs
//   [16w, 16w+16) only. At step top, warp w's lanes 0..15 each poll one
//   producer flag, then __syncwarp. Ring (2-buffer) safety: a CTA writes
//   buf[(t+1)&1] only after its reduction __syncthreads, i.e. after ALL 8
//   warps passed their waits — union of producer sets = all 128 CTAs at
//   step >= t — so every CTA finished READING buf[(t-1)&1] (same parity)
//   before any overwrite. Flag released right after h stores + syncthreads;
//   out[] store is off the critical path; xp prefetched before the wait.
// ---------------------------------------------------------------------------
#define P2_WHF    32768                  // Wh fragments: 128 ksteps x 32 lanes x 8 floats
#define P2_CHF    (16 * 36)              // one chunk: 16 rows x stride 36 = 576 floats
#define P2_RING   (4 * P2_CHF)           // 4-stage ring per warp = 2304 floats
#define P2_SMEMF  (P2_WHF + 8 * P2_RING) // 51200 floats
#define P2_SMEMB  (P2_SMEMF * 4)         // 204800 bytes

__global__ void __launch_bounds__(256, 1) lstm_kernel(
    const float* __restrict__ c0,
    const float* __restrict__ Wfh, const float* __restrict__ Wih,
    const float* __restrict__ Woh, const float* __restrict__ Wch,
    const float* __restrict__ wcf, const float* __restrict__ wci,
    const float* __restrict__ wco,
    float* __restrict__ out)
{
    extern __shared__ float sm[];
    float* whff = sm;                                    // raw fill view
    const float4* whfA = (const float4*)sm;              // gates f,i : [ks*32+lane]
    const float4* whfB = whfA + 128 * 32;                // gates o,c
    float* Aswbase = sm + P2_WHF;                        // 8 warp regions of P2_RING

    const int tid  = threadIdx.x;
    const int warp = tid >> 5, lane = tid & 31;
    const int g    = lane >> 2, tig = lane & 3;
    const int cta  = blockIdx.x;
    const int n0   = cta * 8;

    float* Asw = Aswbase + warp * P2_RING;

    // --- Prologue: build tf32 Wh fragments in SMEM (resident for all steps)
    for (int e = tid; e < 32768; e += 256) {
        int j    = e & 3;
        int ln   = (e >> 2) & 31;
        int ks   = (e >> 7) & 127;
        int half = e >> 14;
        int nt   = half * 2 + (j >> 1);    // gate: 0=f 1=i 2=o 3=c
        int cb   = j & 1;                  // b0 / b1
        int k    = ks * 8 + (ln & 3) + 4 * cb;
        int col  = n0 + (ln >> 2);
        const float* Wsel = (nt == 0) ? Wfh : (nt == 1) ? Wih : (nt == 2) ? Woh : Wch;
        whff[e] = tf32f(Wsel[(size_t)k * NN + col]);
    }

    // --- Per-thread update-cell ownership: 1 row x 2 cols
    const int rh_own = warp >> 1;          // 0..3  (row-chunk)
    const int hb     = warp & 1;           // 0..1  (q-half)
    const int bown   = rh_own * 16 + g + 8 * hb;
    const int nA     = n0 + 2 * tig;

    float2 cv2 = *(const float2*)&c0[bown * NN + nA];
    float creg[2] = {cv2.x, cv2.y};
    float2 pf2 = *(const float2*)&wcf[nA];
    float2 pi2 = *(const float2*)&wci[nA];
    float2 po2 = *(const float2*)&wco[nA];
    const float pfv[2] = {pf2.x, pf2.y};
    const float piv[2] = {pi2.x, pi2.y};
    const float pov[2] = {po2.x, po2.y};

    __syncthreads();   // whf ready

    const int kbase = warp * 128;                 // this warp's k-column base
    const unsigned* myflag = &g_flags[(16 * warp + (lane & 15)) * 8];

    for (int t = 0; t < TT; t++) {
        const float* hsrc = g_hbuf[t & 1];
        float* hdst = g_hbuf[(t + 1) & 1];

        // Prefetch xp BEFORE the wait: no h dependency, DRAM latency hides
        // under the producer spin + GEMM.
        const float* xpt = g_xp + (size_t)t * BB * GG;
        float2 xv[4];
        #pragma unroll
        for (int nt = 0; nt < 4; nt++)
            xv[nt] = *(const float2*)&xpt[(size_t)bown * GG + nt * NN + nA];

        // --- Per-warp producer wait: this warp's 16 producer CTAs at step >= t
        if (t > 0) {
            const unsigned tgt = (unsigned)t;
            if (lane < 16) { while (ld_acq(myflag) < tgt) { } }
            __syncwarp();
        }

        // Accumulators: acc[rh][gate][q] (rh = row-chunk 0..3)
        float acc[4][4][4] __attribute__((aligned(16)));
        #pragma unroll
        for (int a = 0; a < 4; a++)
            #pragma unroll
            for (int b = 0; b < 4; b++)
                #pragma unroll
                for (int q = 0; q < 4; q++) acc[a][b][q] = 0.0f;

        // Stage chunk ci = kc*4 + rh : rows rh*16..+16, kcols kbase+kc*32..+32
        auto stageh = [&](int ci) {
            const int kc = ci >> 2, rh = ci & 3;
            const float* src = hsrc + (size_t)(rh * 16) * NN + kbase + kc * 32;
            float* dst = Asw + (ci & 3) * P2_CHF;
            #pragma unroll
            for (int i = 0; i < 4; i++) {
                int s = lane + 32 * i;              // 16 rows x 8 16B-segs
                int row = s >> 3, off = (s & 7) * 4;
                CP16(smaddr(dst + row * 36 + off), src + (size_t)row * NN + off);
            }
            CPCOMMIT();
        };
        auto waitfor = [&](int ci) {
            if (ci < 13)       cpwait<3>();
            else if (ci == 13) cpwait<2>();
            else if (ci == 14) cpwait<1>();
            else               cpwait<0>();
        };

        stageh(0); stageh(1); stageh(2);

        float4 u0[4], u1[4];                   // Wh fragments for current kc

        #pragma unroll
        for (int kc = 0; kc < 4; kc++) {
            #pragma unroll
            for (int rh = 0; rh < 4; rh++) {
                const int ci = kc * 4 + rh;
                if (ci + 3 < 16) stageh(ci + 3);
                waitfor(ci);
                __syncwarp();
                if (rh == 0) {
                    #pragma unroll
                    for (int kk = 0; kk < 4; kk++) {
                        int ks = warp * 16 + kc * 4 + kk;
                        u0[kk] = whfA[ks * 32 + lane];
                        u1[kk] = whfB[ks * 32 + lane];
                    }
                }
                const float* A = Asw + (ci & 3) * P2_CHF;
                #pragma unroll
                for (int kk = 0; kk < 4; kk++) {
                    unsigned a[4];
                    a[0] = f2b(A[g       * 36 + kk * 8 + tig]);
                    a[1] = f2b(A[(g + 8) * 36 + kk * 8 + tig]);
                    a[2] = f2b(A[g       * 36 + kk * 8 + tig + 4]);
                    a[3] = f2b(A[(g + 8) * 36 + kk * 8 + tig + 4]);
                    mma8(acc[rh][0], a, f2b(u0[kk].x), f2b(u0[kk].y));
                    mma8(acc[rh][1], a, f2b(u0[kk].z), f2b(u0[kk].w));
                    mma8(acc[rh][2], a, f2b(u1[kk].x), f2b(u1[kk].y));
                    mma8(acc[rh][3], a, f2b(u1[kk].z), f2b(u1[kk].w));
                }
                __syncwarp();
            }
        }

        // --- Cross-warp (8-way) reduction via smem (reuse own ring region)
        #pragma unroll
        for (int rh = 0; rh < 4; rh++)
            #pragma unroll
            for (int gt = 0; gt < 4; gt++)
                *(float4*)&Asw[((rh * 4 + gt) * 32 + lane) * 4] = *(const float4*)acc[rh][gt];
        __syncthreads();       // all warps passed waits + finished GEMM; accs visible

        float fin[4][2];
        #pragma unroll
        for (int gt = 0; gt < 4; gt++) {
            float2 s = make_float2(0.f, 0.f);
            #pragma unroll
            for (int w = 0; w < 8; w++) {
                float2 v = *(const float2*)&Aswbase[w * P2_RING +
                            ((rh_own * 4 + gt) * 32 + lane) * 4 + hb * 2];
                s.x += v.x; s.y += v.y;
            }
            fin[gt][0] = s.x; fin[gt][1] = s.y;
        }

        // --- Fused peephole cell update (critical path: h ring store first)
        float hv[2], hr[2];
        #pragma unroll
        for (int q = 0; q < 2; q++) {
            float xf = ((const float*)&xv[0])[q];
            float xi = ((const float*)&xv[1])[q];
            float xo = ((const float*)&xv[2])[q];
            float xc = ((const float*)&xv[3])[q];
            float cp = creg[q];
            float fg = sigf(xf + fin[0][q] + pfv[q] * cp);
            float ig = sigf(xi + fin[1][q] + piv[q] * cp);
            float ct = tanh_fast(xc + fin[3][q]);
            float cn = fg * cp + ig * ct;
            float og = sigf(xo + fin[2][q] + pov[q] * cn);
            float hn = og * tanh_fast(cn);
            creg[q] = cn;
            hv[q] = hn;
            hr[q] = tf32f(hn);
        }
        *(float2*)&hdst[bown * NN + nA] = make_float2(hr[0], hr[1]);

        // Order all h stores before the flag release, then release ASAP.
        __syncthreads();
        if (tid == 0) st_rel(&g_flags[cta * 8], (unsigned)(t + 1));

        // out[] store off the critical path (nobody consumes it)
        *(float2*)&out[((size_t)bown * TT + t) * NN + nA] = make_float2(hv[0], hv[1]);
    }
}

// ---------------------------------------------------------------------------
// Launch. Input order detected from in_sizes (dict vs signature order).
// ---------------------------------------------------------------------------
extern "C" void kernel_launch(void* const* d_in, const int* in_sizes, int n_in,
                              void* d_out, int out_size) {
    const float* x   = (const float*)d_in[0];
    const float* c0  = (const float*)d_in[1];
    const float* h0  = (const float*)d_in[2];

    const float *Wfx, *bf, *Wix, *bi, *Wox, *bo, *Wcx, *bc;
    const float *Wfh, *Wih, *Woh, *Wch, *wcf, *wci, *wco;

    if (in_sizes[5] == NN * NN) {
        Wfx = (const float*)d_in[3];  bf  = (const float*)d_in[4];  Wfh = (const float*)d_in[5];
        Wix = (const float*)d_in[6];  bi  = (const float*)d_in[7];  Wih = (const float*)d_in[8];
        Wox = (const float*)d_in[9];  bo  = (const float*)d_in[10]; Woh = (const float*)d_in[11];
        Wcx = (const float*)d_in[12]; bc  = (const float*)d_in[13]; Wch = (const float*)d_in[14];
        wcf = (const float*)d_in[15]; wci = (const float*)d_in[16]; wco = (const float*)d_in[17];
    } else {
        Wfx = (const float*)d_in[3];  bf  = (const float*)d_in[4];
        Wix = (const float*)d_in[5];  bi  = (const float*)d_in[6];
        Wox = (const float*)d_in[7];  bo  = (const float*)d_in[8];
        Wcx = (const float*)d_in[9];  bc  = (const float*)d_in[10];
        Wfh = (const float*)d_in[11]; Wih = (const float*)d_in[12];
        Woh = (const float*)d_in[13]; Wch = (const float*)d_in[14];
        wcf = (const float*)d_in[15]; wci = (const float*)d_in[16]; wco = (const float*)d_in[17];
    }
    float* out = (float*)d_out;

    cudaFuncSetAttribute(xproj_kernel, cudaFuncAttributeMaxDynamicSharedMemorySize, P1_SMEMB);
    cudaFuncSetAttribute(lstm_kernel,  cudaFuncAttributeMaxDynamicSharedMemorySize, P2_SMEMB);

    init_kernel<<<256, 256>>>(h0);

    dim3 g1(256, 32);
    xproj_kernel<<<g1, 256, P1_SMEMB>>>(x, Wfx, bf, Wix, bi, Wox, bo, Wcx, bc);

    lstm_kernel<<<128, 256, P2_SMEMB>>>(c0, Wfh, Wih, Woh, Wch, wcf, wci, wco, out);
}

// round 8
// speedup vs baseline: 1.5083x; 1.2136x over previous
#include <cuda_runtime.h>
#include <cuda_fp16.h>
#include <cstdint>
#include <cstddef>

// Problem shapes (fixed): B=64, T=512, D=512, N=1024, 4N=4096
#define BB 64
#define TT 512
#define DD 512
#define NN 1024
#define GG 4096

// ---------------------------------------------------------------------------
// Device-global scratch
// ---------------------------------------------------------------------------
__device__ float    g_xp[(size_t)TT * BB * GG];   // [T][B][4N] input projections (fp32)
__device__ __half   g_xh[(size_t)BB * TT * DD];   // x converted to fp16
__device__ __half   g_wxt[(size_t)4 * NN * DD];   // Wx gates transposed [gate][n][k] fp16
__device__ __half   g_hbuf[2][BB * NN];           // parity double-buffered h (fp16)
__device__ unsigned g_flags[128 * 8];             // per-CTA step flags, padded to 32B

// ---------------------------------------------------------------------------
// Helpers
// ---------------------------------------------------------------------------
static __device__ __forceinline__ unsigned h2u(__half2 h) { return *(unsigned*)&h; }

static __device__ __forceinline__ float sigf(float x) { return 1.0f / (1.0f + __expf(-x)); }
static __device__ __forceinline__ float tanh_fast(float x) { return 2.0f * sigf(2.0f * x) - 1.0f; }

static __device__ __forceinline__ unsigned smaddr(const void* p) {
    return (unsigned)__cvta_generic_to_shared(p);
}
#define CP16(d, s)  asm volatile("cp.async.cg.shared.global [%0], [%1], 16;" :: "r"(d), "l"(s))
#define CPCOMMIT()  asm volatile("cp.async.commit_group;")

template <int NPend>
static __device__ __forceinline__ void cpwait() {
    asm volatile("cp.async.wait_group %0;" :: "n"(NPend));
}

// fp16 mma m16n8k16, fp32 accumulate (in place)
static __device__ __forceinline__ void mma16(float* d, const unsigned* a, unsigned b0, unsigned b1) {
    asm volatile(
        "mma.sync.aligned.m16n8k16.row.col.f32.f16.f16.f32 "
        "{%0,%1,%2,%3},{%4,%5,%6,%7},{%8,%9},{%0,%1,%2,%3};"
        : "+f"(d[0]), "+f"(d[1]), "+f"(d[2]), "+f"(d[3])
        : "r"(a[0]), "r"(a[1]), "r"(a[2]), "r"(a[3]), "r"(b0), "r"(b1));
}

static __device__ __forceinline__ unsigned ld_acq(const unsigned* p) {
    unsigned v;
    asm volatile("ld.global.acquire.gpu.u32 %0, [%1];" : "=r"(v) : "l"(p));
    return v;
}
static __device__ __forceinline__ void st_rel(unsigned* p, unsigned v) {
    asm volatile("st.global.release.gpu.u32 [%0], %1;" :: "l"(p), "r"(v));
}

// ---------------------------------------------------------------------------
// Init + input conversion kernels (run every replay; cheap)
// ---------------------------------------------------------------------------
__global__ void init_kernel(const float* __restrict__ h0) {
    int i = blockIdx.x * 256 + threadIdx.x;       // 65536 threads == BB*NN
    g_hbuf[0][i] = __float2half_rn(h0[i]);
    if (i < 128 * 8) g_flags[i] = 0u;
}

__global__ void conv_x_kernel(const float* __restrict__ x) {
    size_t i = (size_t)blockIdx.x * 256 + threadIdx.x;   // BB*TT*DD threads
    g_xh[i] = __float2half_rn(x[i]);
}

// g_wxt[gate][n][k] = fp16(Wgate[k][n])
__global__ void conv_w_kernel(
    const float* __restrict__ Wfx, const float* __restrict__ Wix,
    const float* __restrict__ Wox, const float* __restrict__ Wcx)
{
    size_t e = (size_t)blockIdx.x * 256 + threadIdx.x;   // 4*NN*DD threads
    int k    = (int)(e & (DD - 1));
    int n    = (int)((e >> 9) & (NN - 1));
    int gate = (int)(e >> 19);
    const float* W = (gate == 0) ? Wfx : (gate == 1) ? Wix : (gate == 2) ? Wox : Wcx;
    g_wxt[e] = __float2half_rn(W[(size_t)k * NN + n]);
}

// ---------------------------------------------------------------------------
// Phase 1: xp = x @ [Wfx|Wix|Wox|Wcx] + bias  (fp16 m16n8k16, fp32 acc)
// grid (256 m-blocks, 32 n-blocks), 256 threads, BM=BN=128, BK=32 halfs
// A/B tiles in smem: rows x 36 32-bit words (16 data + pad; banks = 4r+c).
// ---------------------------------------------------------------------------
#define P1_TSTR  36                       // words per row
#define P1_TILE  (128 * P1_TSTR)          // words per tile
#define P1_SMEMB (2 * 2 * P1_TILE * 4)    // 73728 bytes

__global__ void __launch_bounds__(256, 2) xproj_kernel(
    const float* __restrict__ bf, const float* __restrict__ bi,
    const float* __restrict__ bo, const float* __restrict__ bc)
{
    extern __shared__ unsigned smu[];
    unsigned* AsP = smu;                      // [2][128][36]
    unsigned* BsP = smu + 2 * P1_TILE;        // [2][128][36]

    const int tid  = threadIdx.x;
    const int warp = tid >> 5, lane = tid & 31;
    const int g    = lane >> 2, tig = lane & 3;
    const int wm   = warp >> 1, wn = warp & 1;
    const int M0   = blockIdx.x * 128;
    const int gate = blockIdx.y >> 3;
    const int nc0  = (blockIdx.y & 7) * 128;
    const __half* Wt  = g_wxt + (size_t)gate * NN * DD;
    const float* bias = (gate == 0) ? bf : (gate == 1) ? bi : (gate == 2) ? bo : bc;

    float acc[2][8][4];
    #pragma unroll
    for (int a = 0; a < 2; a++)
        #pragma unroll
        for (int b = 0; b < 8; b++)
            #pragma unroll
            for (int q = 0; q < 4; q++) acc[a][b][q] = 0.0f;

    auto stage = [&](int chunk, int buf) {
        const int k0 = chunk * 32;                       // halfs
        unsigned* Ad = AsP + buf * P1_TILE;
        unsigned* Bd = BsP + buf * P1_TILE;
        #pragma unroll
        for (int i = 0; i < 2; i++) {
            int s = tid + 256 * i;                       // 0..511: 128 rows x 4 segs
            int row = s >> 2, seg = s & 3;
            CP16(smaddr(Ad + row * P1_TSTR + seg * 4),
                 g_xh + (size_t)(M0 + row) * DD + k0 + seg * 8);
            CP16(smaddr(Bd + row * P1_TSTR + seg * 4),
                 Wt + (size_t)(nc0 + row) * DD + k0 + seg * 8);
        }
        CPCOMMIT();
    };

    stage(0, 0);
    for (int c = 0; c < 16; c++) {
        if (c + 1 < 16) { stage(c + 1, (c + 1) & 1); cpwait<1>(); }
        else            { cpwait<0>(); }
        __syncthreads();
        const unsigned* A = AsP + (c & 1) * P1_TILE;
        const unsigned* B = BsP + (c & 1) * P1_TILE;
        #pragma unroll
        for (int ks2 = 0; ks2 < 2; ks2++) {
            const int wb = ks2 * 8;
            unsigned a[2][4];
            #pragma unroll
            for (int mf = 0; mf < 2; mf++) {
                int rb = wm * 32 + mf * 16;
                a[mf][0] = A[(rb + g)     * P1_TSTR + wb + tig];
                a[mf][1] = A[(rb + g + 8) * P1_TSTR + wb + tig];
                a[mf][2] = A[(rb + g)     * P1_TSTR + wb + tig + 4];
                a[mf][3] = A[(rb + g + 8) * P1_TSTR + wb + tig + 4];
            }
            #pragma unroll
            for (int nf = 0; nf < 8; nf++) {
                int nb = wn * 64 + nf * 8;
                unsigned b0 = B[(nb + g) * P1_TSTR + wb + tig];
                unsigned b1 = B[(nb + g) * P1_TSTR + wb + tig + 4];
                mma16(acc[0][nf], a[0], b0, b1);
                mma16(acc[1][nf], a[1], b0, b1);
            }
        }
        __syncthreads();
    }

    #pragma unroll
    for (int mf = 0; mf < 2; mf++) {
        #pragma unroll
        for (int rr = 0; rr < 2; rr++) {
            int m = M0 + wm * 32 + mf * 16 + g + rr * 8;
            int b = m >> 9, t = m & 511;
            size_t base = ((size_t)t * BB + b) * GG + (size_t)blockIdx.y * 128;
            #pragma unroll
            for (int nf = 0; nf < 8; nf++) {
                int col = wn * 64 + nf * 8 + 2 * tig;
                float v0 = acc[mf][nf][rr * 2 + 0] + bias[nc0 + col];
                float v1 = acc[mf][nf][rr * 2 + 1] + bias[nc0 + col + 1];
                *(float2*)&g_xp[base + col] = make_float2(v0, v1);
            }
        }
    }
}

// ---------------------------------------------------------------------------
// Phase 2: persistent LSTM recurrence. 128 CTAs x 256 threads (8 warps).
// fp16 h + fp16 Wh fragments, m16n8k16. Warp w owns k in [128w,128w+128).
// Per-warp producer waits (CTAs [16w,16w+16)), 8-deep cp.async ring
// (prefetch distance 6), 8-way smem reduction, fused peephole update.
// ---------------------------------------------------------------------------
#define P2_WHU    16384                   // Wh fragment uints: 64 ks x 2 parts x 32 x 4
#define P2_CHW    (16 * 36)               // chunk: 16 rows x 36 words = 576 words
#define P2_RING   (8 * P2_CHW)            // 8-slot ring per warp = 4608 words
#define P2_SMEMW  (P2_WHU + 8 * P2_RING)  // 53248 words
#define P2_SMEMB  (P2_SMEMW * 4)          // 212992 bytes

__global__ void __launch_bounds__(256, 1) lstm_kernel(
    const float* __restrict__ c0,
    const float* __restrict__ Wfh, const float* __restrict__ Wih,
    const float* __restrict__ Woh, const float* __restrict__ Wch,
    const float* __restrict__ wcf, const float* __restrict__ wci,
    const float* __restrict__ wco,
    float* __restrict__ out)
{
    extern __shared__ unsigned smu[];
    unsigned* whfu = smu;                         // fill view
    const uint4* whf4 = (const uint4*)smu;        // [(ks*2+part)*32 + lane]
    unsigned* Aswbase = smu + P2_WHU;             // 8 warp rings

    const int tid  = threadIdx.x;
    const int warp = tid >> 5, lane = tid & 31;
    const int g    = lane >> 2, tig = lane & 3;
    const int cta  = blockIdx.x;
    const int n0   = cta * 8;

    unsigned* Asw = Aswbase + warp * P2_RING;

    // --- Prologue: build fp16 Wh fragments in SMEM (resident for all steps)
    for (int e = tid; e < P2_WHU; e += 256) {
        int j     = e & 3;
        int lane_ = (e >> 2) & 31;
        int part  = (e >> 7) & 1;
        int ks    = e >> 8;                    // 0..63
        int gate  = part * 2 + (j >> 1);       // 0=f 1=i 2=o 3=c
        int which = j & 1;                     // b0 / b1
        int tg    = lane_ & 3;
        int col   = n0 + (lane_ >> 2);
        int kb    = ks * 16 + 2 * tg + which * 8;
        const float* Wsel = (gate == 0) ? Wfh : (gate == 1) ? Wih : (gate == 2) ? Woh : Wch;
        __half2 v = __floats2half2_rn(Wsel[(size_t)kb * NN + col],
                                      Wsel[(size_t)(kb + 1) * NN + col]);
        whfu[e] = h2u(v);
    }

    // --- Per-thread update-cell ownership: 1 row x 2 cols
    const int rh_own = warp >> 1;          // 0..3  (row-chunk)
    const int hb     = warp & 1;           // 0..1  (q-half)
    const int bown   = rh_own * 16 + g + 8 * hb;
    const int nA     = n0 + 2 * tig;

    float2 cv2 = *(const float2*)&c0[bown * NN + nA];
    float creg[2] = {cv2.x, cv2.y};
    float2 pf2 = *(const float2*)&wcf[nA];
    float2 pi2 = *(const float2*)&wci[nA];
    float2 po2 = *(const float2*)&wco[nA];
    const float pfv[2] = {pf2.x, pf2.y};
    const float piv[2] = {pi2.x, pi2.y};
    const float pov[2] = {po2.x, po2.y};

    __syncthreads();   // whf ready

    const int kbase = warp * 128;                 // this warp's k-base (halfs)
    const unsigned* myflag = &g_flags[(16 * warp + (lane & 15)) * 8];

    for (int t = 0; t < TT; t++) {
        const __half* hsrc = g_hbuf[t & 1];
        __half* hdst = g_hbuf[(t + 1) & 1];

        // Prefetch xp BEFORE the wait (no h dependency)
        const float* xpt = g_xp + (size_t)t * BB * GG;
        float2 xv[4];
        #pragma unroll
        for (int nt = 0; nt < 4; nt++)
            xv[nt] = *(const float2*)&xpt[(size_t)bown * GG + nt * NN + nA];

        // --- Per-warp producer wait
        if (t > 0) {
            const unsigned tgt = (unsigned)t;
            if (lane < 16) { while (ld_acq(myflag) < tgt) { } }
            __syncwarp();
        }

        float acc[4][4][4] __attribute__((aligned(16)));
        #pragma unroll
        for (int a = 0; a < 4; a++)
            #pragma unroll
            for (int b = 0; b < 4; b++)
                #pragma unroll
                for (int q = 0; q < 4; q++) acc[a][b][q] = 0.0f;

        // Stage chunk ci = kc*4 + rh : rows rh*16..+16, k halfs kbase+kc*32..+32
        auto stageh = [&](int ci) {
            const int kc = ci >> 2, rh = ci & 3;
            const __half* src = hsrc + (size_t)(rh * 16) * NN + kbase + kc * 32;
            unsigned* dst = Asw + (ci & 7) * P2_CHW;
            #pragma unroll
            for (int i = 0; i < 2; i++) {
                int s = lane + 32 * i;                // 16 rows x 4 16B-segs
                int row = s >> 2, seg = s & 3;
                CP16(smaddr(dst + row * 36 + seg * 4), src + (size_t)row * NN + seg * 8);
            }
            CPCOMMIT();
        };
        auto waitfor = [&](int ci) {
            if (ci <= 9)       cpwait<6>();
            else if (ci == 10) cpwait<5>();
            else if (ci == 11) cpwait<4>();
            else if (ci == 12) cpwait<3>();
            else if (ci == 13) cpwait<2>();
            else if (ci == 14) cpwait<1>();
            else               cpwait<0>();
        };

        stageh(0); stageh(1); stageh(2); stageh(3); stageh(4); stageh(5);

        uint4 uA[2], uB[2];                    // Wh fragments for current kc (2 ksteps)

        #pragma unroll
        for (int kc = 0; kc < 4; kc++) {
            #pragma unroll
            for (int rh = 0; rh < 4; rh++) {
                const int ci = kc * 4 + rh;
                if (ci + 6 < 16) stageh(ci + 6);
                waitfor(ci);
                __syncwarp();
                if (rh == 0) {
                    #pragma unroll
                    for (int ks2 = 0; ks2 < 2; ks2++) {
                        int ks = warp * 8 + kc * 2 + ks2;
                        uA[ks2] = whf4[(ks * 2 + 0) * 32 + lane];
                        uB[ks2] = whf4[(ks * 2 + 1) * 32 + lane];
                    }
                }
                const unsigned* A = Asw + (ci & 7) * P2_CHW;
                #pragma unroll
                for (int ks2 = 0; ks2 < 2; ks2++) {
                    const int wb = ks2 * 8;
                    unsigned a[4];
                    a[0] = A[g       * 36 + wb + tig];
                    a[1] = A[(g + 8) * 36 + wb + tig];
                    a[2] = A[g       * 36 + wb + tig + 4];
                    a[3] = A[(g + 8) * 36 + wb + tig + 4];
                    mma16(acc[rh][0], a, uA[ks2].x, uA[ks2].y);   // forget
                    mma16(acc[rh][1], a, uA[ks2].z, uA[ks2].w);   // input
                    mma16(acc[rh][2], a, uB[ks2].x, uB[ks2].y);   // output
                    mma16(acc[rh][3], a, uB[ks2].z, uB[ks2].w);   // cell
                }
                __syncwarp();
            }
        }

        // --- Cross-warp (8-way) reduction via smem (reuse own ring region)
        float* Aswf = (float*)Asw;
        #pragma unroll
        for (int rh = 0; rh < 4; rh++)
            #pragma unroll
            for (int gt = 0; gt < 4; gt++)
                *(float4*)&Aswf[((rh * 4 + gt) * 32 + lane) * 4] = *(const float4*)acc[rh][gt];
        __syncthreads();

        float fin[4][2];
        #pragma unroll
        for (int gt = 0; gt < 4; gt++) {
            float2 s = make_float2(0.f, 0.f);
            #pragma unroll
            for (int w = 0; w < 8; w++) {
                float2 v = *(const float2*)&((float*)(Aswbase + w * P2_RING))[
                            ((rh_own * 4 + gt) * 32 + lane) * 4 + hb * 2];
                s.x += v.x; s.y += v.y;
            }
            fin[gt][0] = s.x; fin[gt][1] = s.y;
        }

        // --- Fused peephole cell update (h ring store first)
        float hv[2];
        #pragma unroll
        for (int q = 0; q < 2; q++) {
            float xf = ((const float*)&xv[0])[q];
            float xi = ((const float*)&xv[1])[q];
            float xo = ((const float*)&xv[2])[q];
            float xc = ((const float*)&xv[3])[q];
            float cp = creg[q];
            float fg = sigf(xf + fin[0][q] + pfv[q] * cp);
            float ig = sigf(xi + fin[1][q] + piv[q] * cp);
            float ct = tanh_fast(xc + fin[3][q]);
            float cn = fg * cp + ig * ct;
            float og = sigf(xo + fin[2][q] + pov[q] * cn);
            float hn = og * tanh_fast(cn);
            creg[q] = cn;
            hv[q] = hn;
        }
        *(__half2*)&hdst[bown * NN + nA] = __floats2half2_rn(hv[0], hv[1]);

        // Order all h stores before the flag release, then release ASAP.
        __syncthreads();
        if (tid == 0) st_rel(&g_flags[cta * 8], (unsigned)(t + 1));

        // out[] store off the critical path
        *(float2*)&out[((size_t)bown * TT + t) * NN + nA] = make_float2(hv[0], hv[1]);
    }
}

// ---------------------------------------------------------------------------
// Launch. Input order detected from in_sizes (dict vs signature order).
// ---------------------------------------------------------------------------
extern "C" void kernel_launch(void* const* d_in, const int* in_sizes, int n_in,
                              void* d_out, int out_size) {
    const float* x   = (const float*)d_in[0];
    const float* c0  = (const float*)d_in[1];
    const float* h0  = (const float*)d_in[2];

    const float *Wfx, *bf, *Wix, *bi, *Wox, *bo, *Wcx, *bc;
    const float *Wfh, *Wih, *Woh, *Wch, *wcf, *wci, *wco;

    if (in_sizes[5] == NN * NN) {
        Wfx = (const float*)d_in[3];  bf  = (const float*)d_in[4];  Wfh = (const float*)d_in[5];
        Wix = (const float*)d_in[6];  bi  = (const float*)d_in[7];  Wih = (const float*)d_in[8];
        Wox = (const float*)d_in[9];  bo  = (const float*)d_in[10]; Woh = (const float*)d_in[11];
        Wcx = (const float*)d_in[12]; bc  = (const float*)d_in[13]; Wch = (const float*)d_in[14];
        wcf = (const float*)d_in[15]; wci = (const float*)d_in[16]; wco = (const float*)d_in[17];
    } else {
        Wfx = (const float*)d_in[3];  bf  = (const float*)d_in[4];
        Wix = (const float*)d_in[5];  bi  = (const float*)d_in[6];
        Wox = (const float*)d_in[7];  bo  = (const float*)d_in[8];
        Wcx = (const float*)d_in[9];  bc  = (const float*)d_in[10];
        Wfh = (const float*)d_in[11]; Wih = (const float*)d_in[12];
        Woh = (const float*)d_in[13]; Wch = (const float*)d_in[14];
        wcf = (const float*)d_in[15]; wci = (const float*)d_in[16]; wco = (const float*)d_in[17];
    }
    float* out = (float*)d_out;

    cudaFuncSetAttribute(xproj_kernel, cudaFuncAttributeMaxDynamicSharedMemorySize, P1_SMEMB);
    cudaFuncSetAttribute(lstm_kernel,  cudaFuncAttributeMaxDynamicSharedMemorySize, P2_SMEMB);

    init_kernel<<<256, 256>>>(h0);
    conv_x_kernel<<<(BB * TT * DD) / 256, 256>>>(x);
    conv_w_kernel<<<(4 * NN * DD) / 256, 256>>>(Wfx, Wix, Wox, Wcx);

    dim3 g1(256, 32);
    xproj_kernel<<<g1, 256, P1_SMEMB>>>(bf, bi, bo, bc);

    lstm_kernel<<<128, 256, P2_SMEMB>>>(c0, Wfh, Wih, Woh, Wch, wcf, wci, wco, out);
}

// round 10
// speedup vs baseline: 1.5589x; 1.0335x over previous
#include <cuda_runtime.h>
#include <cuda_fp16.h>
#include <cstdint>
#include <cstddef>

// Problem shapes (fixed): B=64, T=512, D=512, N=1024, 4N=4096
#define BB 64
#define TT 512
#define DD 512
#define NN 1024
#define GG 4096

// ---------------------------------------------------------------------------
// Device-global scratch
// ---------------------------------------------------------------------------
__device__ float    g_xp[(size_t)TT * BB * GG];   // [T][B][4N] input projections (fp32)
__device__ __half   g_xh[(size_t)BB * TT * DD];   // x converted to fp16
__device__ __half   g_wxt[(size_t)4 * NN * DD];   // Wx gates transposed [gate][n][k] fp16
__device__ __half   g_hbuf[2][BB * NN];           // parity double-buffered h (fp16)
__device__ unsigned g_flags[128 * 8];             // per-CTA step flags, padded to 32B

// ---------------------------------------------------------------------------
// Helpers
// ---------------------------------------------------------------------------
static __device__ __forceinline__ unsigned h2u(__half2 h) { return *(unsigned*)&h; }

static __device__ __forceinline__ float sigf(float x) { return 1.0f / (1.0f + __expf(-x)); }
static __device__ __forceinline__ float tanh_fast(float x) { return 2.0f * sigf(2.0f * x) - 1.0f; }

static __device__ __forceinline__ unsigned smaddr(const void* p) {
    return (unsigned)__cvta_generic_to_shared(p);
}
#define CP16(d, s)  asm volatile("cp.async.cg.shared.global [%0], [%1], 16;" :: "r"(d), "l"(s))
#define CPCOMMIT()  asm volatile("cp.async.commit_group;")

template <int NPend>
static __device__ __forceinline__ void cpwait() {
    asm volatile("cp.async.wait_group %0;" :: "n"(NPend));
}

// ldmatrix x4: 4 8x8 b16 tiles -> 4 regs (lane l of each tile: row l>>2, pair l&3)
static __device__ __forceinline__ void ldsm4(unsigned* r, unsigned addr) {
    asm volatile("ldmatrix.sync.aligned.m8n8.x4.shared.b16 {%0,%1,%2,%3}, [%4];"
        : "=r"(r[0]), "=r"(r[1]), "=r"(r[2]), "=r"(r[3]) : "r"(addr));
}

// fp16 mma m16n8k16, fp32 accumulate (in place)
static __device__ __forceinline__ void mma16(float* d, const unsigned* a, unsigned b0, unsigned b1) {
    asm volatile(
        "mma.sync.aligned.m16n8k16.row.col.f32.f16.f16.f32 "
        "{%0,%1,%2,%3},{%4,%5,%6,%7},{%8,%9},{%0,%1,%2,%3};"
        : "+f"(d[0]), "+f"(d[1]), "+f"(d[2]), "+f"(d[3])
        : "r"(a[0]), "r"(a[1]), "r"(a[2]), "r"(a[3]), "r"(b0), "r"(b1));
}

static __device__ __forceinline__ unsigned ld_acq(const unsigned* p) {
    unsigned v;
    asm volatile("ld.global.acquire.gpu.u32 %0, [%1];" : "=r"(v) : "l"(p));
    return v;
}
static __device__ __forceinline__ void st_rel(unsigned* p, unsigned v) {
    asm volatile("st.global.release.gpu.u32 [%0], %1;" :: "l"(p), "r"(v));
}

// ---------------------------------------------------------------------------
// Init + input conversion kernels (run every replay; cheap)
// ---------------------------------------------------------------------------
__global__ void init_kernel(const float* __restrict__ h0) {
    int i = blockIdx.x * 256 + threadIdx.x;       // 65536 threads == BB*NN
    g_hbuf[0][i] = __float2half_rn(h0[i]);
    if (i < 128 * 8) g_flags[i] = 0u;
}

__global__ void conv_x_kernel(const float* __restrict__ x) {
    size_t i = (size_t)blockIdx.x * 256 + threadIdx.x;   // BB*TT*DD threads
    g_xh[i] = __float2half_rn(x[i]);
}

// g_wxt[gate][n][k] = fp16(Wgate[k][n])
__global__ void conv_w_kernel(
    const float* __restrict__ Wfx, const float* __restrict__ Wix,
    const float* __restrict__ Wox, const float* __restrict__ Wcx)
{
    size_t e = (size_t)blockIdx.x * 256 + threadIdx.x;   // 4*NN*DD threads
    int k    = (int)(e & (DD - 1));
    int n    = (int)((e >> 9) & (NN - 1));
    int gate = (int)(e >> 19);
    const float* W = (gate == 0) ? Wfx : (gate == 1) ? Wix : (gate == 2) ? Wox : Wcx;
    g_wxt[e] = __float2half_rn(W[(size_t)k * NN + n]);
}

// ---------------------------------------------------------------------------
// Phase 1: xp = x @ [Wfx|Wix|Wox|Wcx] + bias  (fp16 m16n8k16, fp32 acc)
// grid (256 m-blocks, 32 n-blocks), 256 threads, BM=BN=128, BK=32 halfs.
// Fragment loads via ldmatrix.x4 (conflict-free under stride-36 padding).
// ---------------------------------------------------------------------------
#define P1_TSTR  36                       // words per row
#define P1_TILE  (128 * P1_TSTR)          // words per tile
#define P1_SMEMB (2 * 2 * P1_TILE * 4)    // 73728 bytes

__global__ void __launch_bounds__(256, 2) xproj_kernel(
    const float* __restrict__ bf, const float* __restrict__ bi,
    const float* __restrict__ bo, const float* __restrict__ bc)
{
    extern __shared__ unsigned smu[];
    unsigned* AsP = smu;                      // [2][128][36]
    unsigned* BsP = smu + 2 * P1_TILE;        // [2][128][36]

    const int tid  = threadIdx.x;
    const int warp = tid >> 5, lane = tid & 31;
    const int g    = lane >> 2, tig = lane & 3;
    const int wm   = warp >> 1, wn = warp & 1;
    const int M0   = blockIdx.x * 128;
    const int gate = blockIdx.y >> 3;
    const int nc0  = (blockIdx.y & 7) * 128;
    const __half* Wt  = g_wxt + (size_t)gate * NN * DD;
    const float* bias = (gate == 0) ? bf : (gate == 1) ? bi : (gate == 2) ? bo : bc;

    // LDSM address bases (bytes), before buffer/k offsets
    const unsigned sb = smaddr(smu);
    // A x4 tile for mf: rows wm*32+mf*16 + (lane&15), seg (lane>>4)*4 words
    unsigned aoff = sb + (((wm * 32 + (lane & 15)) * P1_TSTR + (lane >> 4) * 4) << 2);
    // B x4 group nfp: rows wn*64+nfp*16 + (lane&7) + ((lane>>4)&1)*8, seg ((lane>>3)&1)*4
    unsigned boff0 = sb + ((2 * P1_TILE +
                     ((wn * 64 + (lane & 7) + ((lane >> 4) & 1) * 8) * P1_TSTR +
                      ((lane >> 3) & 1) * 4)) << 2);

    float acc[2][8][4];
    #pragma unroll
    for (int a = 0; a < 2; a++)
        #pragma unroll
        for (int b = 0; b < 8; b++)
            #pragma unroll
            for (int q = 0; q < 4; q++) acc[a][b][q] = 0.0f;

    auto stage = [&](int chunk, int buf) {
        const int k0 = chunk * 32;                       // halfs
        unsigned* Ad = AsP + buf * P1_TILE;
        unsigned* Bd = BsP + buf * P1_TILE;
        #pragma unroll
        for (int i = 0; i < 2; i++) {
            int s = tid + 256 * i;                       // 0..511: 128 rows x 4 segs
            int row = s >> 2, seg = s & 3;
            CP16(smaddr(Ad + row * P1_TSTR + seg * 4),
                 g_xh + (size_t)(M0 + row) * DD + k0 + seg * 8);
            CP16(smaddr(Bd + row * P1_TSTR + seg * 4),
                 Wt + (size_t)(nc0 + row) * DD + k0 + seg * 8);
        }
        CPCOMMIT();
    };

    stage(0, 0);
    for (int c = 0; c < 16; c++) {
        if (c + 1 < 16) { stage(c + 1, (c + 1) & 1); cpwait<1>(); }
        else            { cpwait<0>(); }
        __syncthreads();
        const unsigned bufB = (unsigned)((c & 1) * P1_TILE * 4);
        #pragma unroll
        for (int ks2 = 0; ks2 < 2; ks2++) {
            const unsigned kB = bufB + ks2 * 32;         // 8 words = 32 bytes
            unsigned a[2][4];
            ldsm4(a[0], aoff + kB);
            ldsm4(a[1], aoff + kB + 16 * P1_TSTR * 4);
            #pragma unroll
            for (int nfp = 0; nfp < 4; nfp++) {
                unsigned b4[4];
                ldsm4(b4, boff0 + kB + nfp * 16 * P1_TSTR * 4);
                mma16(acc[0][2 * nfp],     a[0], b4[0], b4[1]);
                mma16(acc[1][2 * nfp],     a[1], b4[0], b4[1]);
                mma16(acc[0][2 * nfp + 1], a[0], b4[2], b4[3]);
                mma16(acc[1][2 * nfp + 1], a[1], b4[2], b4[3]);
            }
        }
        __syncthreads();
    }

    #pragma unroll
    for (int mf = 0; mf < 2; mf++) {
        #pragma unroll
        for (int rr = 0; rr < 2; rr++) {
            int m = M0 + wm * 32 + mf * 16 + g + rr * 8;
            int b = m >> 9, t = m & 511;
            size_t base = ((size_t)t * BB + b) * GG + (size_t)blockIdx.y * 128;
            #pragma unroll
            for (int nf = 0; nf < 8; nf++) {
                int col = wn * 64 + nf * 8 + 2 * tig;
                float v0 = acc[mf][nf][rr * 2 + 0] + bias[nc0 + col];
                float v1 = acc[mf][nf][rr * 2 + 1] + bias[nc0 + col + 1];
                *(float2*)&g_xp[base + col] = make_float2(v0, v1);
            }
        }
    }
}

// ---------------------------------------------------------------------------
// Phase 2: persistent LSTM recurrence. 128 CTAs x 256 threads (8 warps).
// fp16 h + fp16 Wh fragments, m16n8k16. Warp w owns k in [128w,128w+128).
//
// PER-KC PRODUCER WAITS: chunk group kc depends on only 4 CTAs
// [16w+4kc, 16w+4kc+4). Waits are staggered (kc0 upfront; kc+1 waited just
// before its first stage), so stragglers overlap GEMM of ready chunks.
// Ring invariant unchanged: h-store happens after the reduction
// __syncthreads, i.e. after ALL warps completed ALL kc waits (union = all
// 128 CTAs at step >= t), so buf[(t-1)&1] is fully consumed before reuse.
// 4-deep ring, stage-ahead 4 (slot freed before restage).
// ---------------------------------------------------------------------------
#define P2_WHU    16384                   // Wh fragment uints: 64 ks x 2 parts x 32 x 4
#define P2_CHW    (16 * 36)               // chunk: 16 rows x 36 words = 576 words
#define P2_RING   (4 * P2_CHW)            // 4-slot ring per warp = 2304 words
#define P2_SMEMW  (P2_WHU + 8 * P2_RING)  // 34816 words
#define P2_SMEMB  (P2_SMEMW * 4)          // 139264 bytes

__global__ void __launch_bounds__(256, 1) lstm_kernel(
    const float* __restrict__ c0,
    const float* __restrict__ Wfh, const float* __restrict__ Wih,
    const float* __restrict__ Woh, const float* __restrict__ Wch,
    const float* __restrict__ wcf, const float* __restrict__ wci,
    const float* __restrict__ wco,
    float* __restrict__ out)
{
    extern __shared__ unsigned smu[];
    unsigned* whfu = smu;                         // fill view
    const uint4* whf4 = (const uint4*)smu;        // [(ks*2+part)*32 + lane]
    unsigned* Aswbase = smu + P2_WHU;             // 8 warp rings

    const int tid  = threadIdx.x;
    const int warp = tid >> 5, lane = tid & 31;
    const int g    = lane >> 2, tig = lane & 3;
    const int cta  = blockIdx.x;
    const int n0   = cta * 8;

    unsigned* Asw = Aswbase + warp * P2_RING;

    // LDSM A-frag base address (bytes): rows lane&15, seg (lane>>4)*4 words
    const unsigned aaddr0 = smaddr(Asw) + (((lane & 15) * 36 + (lane >> 4) * 4) << 2);

    // --- Prologue: build fp16 Wh fragments in SMEM (resident for all steps)
    for (int e = tid; e < P2_WHU; e += 256) {
        int j     = e & 3;
        int lane_ = (e >> 2) & 31;
        int part  = (e >> 7) & 1;
        int ks    = e >> 8;                    // 0..63
        int gate  = part * 2 + (j >> 1);       // 0=f 1=i 2=o 3=c
        int which = j & 1;                     // b0 / b1
        int tg    = lane_ & 3;
        int col   = n0 + (lane_ >> 2);
        int kb    = ks * 16 + 2 * tg + which * 8;
        const float* Wsel = (gate == 0) ? Wfh : (gate == 1) ? Wih : (gate == 2) ? Woh : Wch;
        __half2 v = __floats2half2_rn(Wsel[(size_t)kb * NN + col],
                                      Wsel[(size_t)(kb + 1) * NN + col]);
        whfu[e] = h2u(v);
    }

    // --- Per-thread update-cell ownership: 1 row x 2 cols
    const int rh_own = warp >> 1;          // 0..3  (row-chunk)
    const int hb     = warp & 1;           // 0..1  (q-half)
    const int bown   = rh_own * 16 + g + 8 * hb;
    const int nA     = n0 + 2 * tig;

    float2 cv2 = *(const float2*)&c0[bown * NN + nA];
    float creg[2] = {cv2.x, cv2.y};
    float2 pf2 = *(const float2*)&wcf[nA];
    float2 pi2 = *(const float2*)&wci[nA];
    float2 po2 = *(const float2*)&wco[nA];
    const float pfv[2] = {pf2.x, pf2.y};
    const float piv[2] = {pi2.x, pi2.y};
    const float pov[2] = {po2.x, po2.y};

    __syncthreads();   // whf ready

    const int kbase = warp * 128;                 // this warp's k-base (halfs)

    for (int t = 0; t < TT; t++) {
        const __half* hsrc = g_hbuf[t & 1];
        __half* hdst = g_hbuf[(t + 1) & 1];

        // Prefetch xp BEFORE any wait (no h dependency)
        const float* xpt = g_xp + (size_t)t * BB * GG;
        float2 xv[4];
        #pragma unroll
        for (int nt = 0; nt < 4; nt++)
            xv[nt] = *(const float2*)&xpt[(size_t)bown * GG + nt * NN + nA];

        // Per-kc producer wait: 4 CTAs [16w+4kc, +4) at step >= t
        auto waitkc = [&](int kc) {
            if (t > 0) {
                const unsigned tgt = (unsigned)t;
                if (lane < 4) {
                    const unsigned* f = &g_flags[(16 * warp + 4 * kc + lane) * 8];
                    while (ld_acq(f) < tgt) { }
                }
                __syncwarp();
            }
        };

        float acc[4][4][4] __attribute__((aligned(16)));
        #pragma unroll
        for (int a = 0; a < 4; a++)
            #pragma unroll
            for (int b = 0; b < 4; b++)
                #pragma unroll
                for (int q = 0; q < 4; q++) acc[a][b][q] = 0.0f;

        // Stage chunk ci = kc*4 + rh : rows rh*16..+16, k halfs kbase+kc*32..+32
        auto stageh = [&](int ci) {
            const int kc = ci >> 2, rh = ci & 3;
            const __half* src = hsrc + (size_t)(rh * 16) * NN + kbase + kc * 32;
            unsigned* dst = Asw + (ci & 3) * P2_CHW;
            #pragma unroll
            for (int i = 0; i < 2; i++) {
                int s = lane + 32 * i;                // 16 rows x 4 16B-segs
                int row = s >> 2, seg = s & 3;
                CP16(smaddr(dst + row * 36 + seg * 4), src + (size_t)row * NN + seg * 8);
            }
            CPCOMMIT();
        };
        auto waitcp = [&](int ci) {
            if (ci <= 12)      cpwait<3>();
            else if (ci == 13) cpwait<2>();
            else if (ci == 14) cpwait<1>();
            else               cpwait<0>();
        };

        waitkc(0);
        stageh(0); stageh(1); stageh(2); stageh(3);

        uint4 uA[2], uB[2];                    // Wh fragments for current kc (2 ksteps)

        #pragma unroll
        for (int kc = 0; kc < 4; kc++) {
            #pragma unroll
            for (int rh = 0; rh < 4; rh++) {
                const int ci = kc * 4 + rh;
                waitcp(ci);
                __syncwarp();
                if (rh == 0) {
                    #pragma unroll
                    for (int ks2 = 0; ks2 < 2; ks2++) {
                        int ks = warp * 8 + kc * 2 + ks2;
                        uA[ks2] = whf4[(ks * 2 + 0) * 32 + lane];
                        uB[ks2] = whf4[(ks * 2 + 1) * 32 + lane];
                    }
                }
                const unsigned abase = aaddr0 + (unsigned)((ci & 3) * P2_CHW * 4);
                #pragma unroll
                for (int ks2 = 0; ks2 < 2; ks2++) {
                    unsigned a[4];
                    ldsm4(a, abase + ks2 * 32);
                    mma16(acc[rh][0], a, uA[ks2].x, uA[ks2].y);   // forget
                    mma16(acc[rh][1], a, uA[ks2].z, uA[ks2].w);   // input
                    mma16(acc[rh][2], a, uB[ks2].x, uB[ks2].y);   // output
                    mma16(acc[rh][3], a, uB[ks2].z, uB[ks2].w);   // cell
                }
                __syncwarp();   // all lanes done reading slot before restage
                if (ci + 4 < 16) {
                    if (((ci + 4) & 3) == 0) waitkc((ci + 4) >> 2);
                    stageh(ci + 4);
                }
            }
        }

        // --- Cross-warp (8-way) reduction via smem (reuse own ring region)
        float* Aswf = (float*)Asw;
        #pragma unroll
        for (int rh = 0; rh < 4; rh++)
            #pragma unroll
            for (int gt = 0; gt < 4; gt++)
                *(float4*)&Aswf[((rh * 4 + gt) * 32 + lane) * 4] = *(const float4*)acc[rh][gt];
        __syncthreads();       // all warps passed all waits + finished GEMM

        float fin[4][2];
        #pragma unroll
        for (int gt = 0; gt < 4; gt++) {
            float2 s = make_float2(0.f, 0.f);
            #pragma unroll
            for (int w = 0; w < 8; w++) {
                float2 v = *(const float2*)&((float*)(Aswbase + w * P2_RING))[
                            ((rh_own * 4 + gt) * 32 + lane) * 4 + hb * 2];
                s.x += v.x; s.y += v.y;
            }
            fin[gt][0] = s.x; fin[gt][1] = s.y;
        }

        // --- Fused peephole cell update (h ring store first)
        float hv[2];
        #pragma unroll
        for (int q = 0; q < 2; q++) {
            float xf = ((const float*)&xv[0])[q];
            float xi = ((const float*)&xv[1])[q];
            float xo = ((const float*)&xv[2])[q];
            float xc = ((const float*)&xv[3])[q];
            float cp = creg[q];
            float fg = sigf(xf + fin[0][q] + pfv[q] * cp);
            float ig = sigf(xi + fin[1][q] + piv[q] * cp);
            float ct = tanh_fast(xc + fin[3][q]);
            float cn = fg * cp + ig * ct;
            float og = sigf(xo + fin[2][q] + pov[q] * cn);
            float hn = og * tanh_fast(cn);
            creg[q] = cn;
            hv[q] = hn;
        }
        *(__half2*)&hdst[bown * NN + nA] = __floats2half2_rn(hv[0], hv[1]);

        // Order all h stores before the flag release, then release ASAP.
        __syncthreads();
        if (tid == 0) st_rel(&g_flags[cta * 8], (unsigned)(t + 1));

        // out[] store off the critical path
        *(float2*)&out[((size_t)bown * TT + t) * NN + nA] = make_float2(hv[0], hv[1]);
    }
}

// ---------------------------------------------------------------------------
// Launch. Input order detected from in_sizes (dict vs signature order).
// ---------------------------------------------------------------------------
extern "C" void kernel_launch(void* const* d_in, const int* in_sizes, int n_in,
                              void* d_out, int out_size) {
    const float* x   = (const float*)d_in[0];
    const float* c0  = (const float*)d_in[1];
    const float* h0  = (const float*)d_in[2];

    const float *Wfx, *bf, *Wix, *bi, *Wox, *bo, *Wcx, *bc;
    const float *Wfh, *Wih, *Woh, *Wch, *wcf, *wci, *wco;

    if (in_sizes[5] == NN * NN) {
        Wfx = (const float*)d_in[3];  bf  = (const float*)d_in[4];  Wfh = (const float*)d_in[5];
        Wix = (const float*)d_in[6];  bi  = (const float*)d_in[7];  Wih = (const float*)d_in[8];
        Wox = (const float*)d_in[9];  bo  = (const float*)d_in[10]; Woh = (const float*)d_in[11];
        Wcx = (const float*)d_in[12]; bc  = (const float*)d_in[13]; Wch = (const float*)d_in[14];
        wcf = (const float*)d_in[15]; wci = (const float*)d_in[16]; wco = (const float*)d_in[17];
    } else {
        Wfx = (const float*)d_in[3];  bf  = (const float*)d_in[4];
        Wix = (const float*)d_in[5];  bi  = (const float*)d_in[6];
        Wox = (const float*)d_in[7];  bo  = (const float*)d_in[8];
        Wcx = (const float*)d_in[9];  bc  = (const float*)d_in[10];
        Wfh = (const float*)d_in[11]; Wih = (const float*)d_in[12];
        Woh = (const float*)d_in[13]; Wch = (const float*)d_in[14];
        wcf = (const float*)d_in[15]; wci = (const float*)d_in[16]; wco = (const float*)d_in[17];
    }
    float* out = (float*)d_out;

    cudaFuncSetAttribute(xproj_kernel, cudaFuncAttributeMaxDynamicSharedMemorySize, P1_SMEMB);
    cudaFuncSetAttribute(lstm_kernel,  cudaFuncAttributeMaxDynamicSharedMemorySize, P2_SMEMB);

    init_kernel<<<256, 256>>>(h0);
    conv_x_kernel<<<(BB * TT * DD) / 256, 256>>>(x);
    conv_w_kernel<<<(4 * NN * DD) / 256, 256>>>(Wfx, Wix, Wox, Wcx);

    dim3 g1(256, 32);
    xproj_kernel<<<g1, 256, P1_SMEMB>>>(bf, bi, bo, bc);

    lstm_kernel<<<128, 256, P2_SMEMB>>>(c0, Wfh, Wih, Woh, Wch, wcf, wci, wco, out);
}